// round 1
// baseline (speedup 1.0000x reference)
#include <cuda_runtime.h>

#define NB 8
#define C 512
#define T 4096
#define GROUPS 32
#define CPG (C / GROUPS)      // 16
#define GSZ (CPG * T)         // 65536 elements per group

// Scratch (device globals; no allocations allowed)
__device__ float g_h[(size_t)NB * C * T];        // normalized x, [N][C][T]
__device__ float g_q[(size_t)NB * C * T];        // [N][C][T] (channel-major)
__device__ float g_k[(size_t)NB * C * T];        // [N][C][T]
__device__ float g_v[(size_t)NB * C * T];        // [N][C][T]
__device__ float g_o[(size_t)NB * T * C];        // [N][T][C]
__device__ float g_attn[(size_t)NB * T * T];     // [N][T][T]  (512 MB)

// ---------------------------------------------------------------------------
// GroupNorm: one block per (n, group)
// ---------------------------------------------------------------------------
__global__ void __launch_bounds__(256) gn_kernel(const float* __restrict__ x,
                                                 const float* __restrict__ w,
                                                 const float* __restrict__ b) {
    int n = blockIdx.x >> 5;
    int g = blockIdx.x & 31;
    const float4* xp = (const float4*)(x + ((size_t)n * C + g * CPG) * T);
    const int NV = GSZ / 4;  // 16384 float4s

    float s = 0.f, s2 = 0.f;
    for (int i = threadIdx.x; i < NV; i += 256) {
        float4 v = xp[i];
        s  += v.x + v.y + v.z + v.w;
        s2 += v.x * v.x + v.y * v.y + v.z * v.z + v.w * v.w;
    }
    __shared__ float rs[32], rs2[32];
    int lid = threadIdx.x & 31, wid = threadIdx.x >> 5;
#pragma unroll
    for (int o = 16; o; o >>= 1) {
        s  += __shfl_xor_sync(0xffffffffu, s, o);
        s2 += __shfl_xor_sync(0xffffffffu, s2, o);
    }
    if (lid == 0) { rs[wid] = s; rs2[wid] = s2; }
    __syncthreads();
    if (wid == 0) {
        s  = (lid < 8) ? rs[lid]  : 0.f;
        s2 = (lid < 8) ? rs2[lid] : 0.f;
#pragma unroll
        for (int o = 4; o; o >>= 1) {
            s  += __shfl_xor_sync(0xffffffffu, s, o);
            s2 += __shfl_xor_sync(0xffffffffu, s2, o);
        }
        if (lid == 0) { rs[0] = s; rs2[0] = s2; }
    }
    __syncthreads();
    float mean = rs[0] * (1.f / GSZ);
    float var  = rs2[0] * (1.f / GSZ) - mean * mean;
    float inv  = rsqrtf(var + 1e-5f);

    float4* hp = (float4*)(g_h + ((size_t)n * C + g * CPG) * T);
    for (int i = threadIdx.x; i < NV; i += 256) {
        int c = g * CPG + (i >> 10);           // T/4 = 1024 float4 per channel
        float sc = w[c] * inv;
        float sb = b[c] - mean * sc;
        float4 v = xp[i];
        v.x = v.x * sc + sb;  v.y = v.y * sc + sb;
        v.z = v.z * sc + sb;  v.w = v.w * sc + sb;
        hp[i] = v;
    }
}

// ---------------------------------------------------------------------------
// 128x128x8 SIMT sgemm tile core. As/Bs hold A[k][m], B[k][n].
// ATRANS: A global layout [M][K] (k-contig)  else [K][M] (m-contig)
// BTRANS: B global layout [N][K] (k-contig)  else [K][N] (n-contig)
// ---------------------------------------------------------------------------
template <bool ATRANS, bool BTRANS>
__device__ __forceinline__ void sgemm_tile(const float* __restrict__ Ag, int lda,
                                           const float* __restrict__ Bg, int ldb,
                                           int K, float acc[8][8]) {
    __shared__ float As[8][128];
    __shared__ float Bs[8][128];
    const int t = threadIdx.x;
    const int row0 = (t >> 4) * 4;
    const int col0 = (t & 15) * 4;

    for (int k0 = 0; k0 < K; k0 += 8) {
        if (ATRANS) {
            int ar = t >> 1, ak = (t & 1) * 4;
            float4 v = *(const float4*)(Ag + (size_t)ar * lda + k0 + ak);
            As[ak + 0][ar] = v.x; As[ak + 1][ar] = v.y;
            As[ak + 2][ar] = v.z; As[ak + 3][ar] = v.w;
        } else {
            int ar = t >> 5, ac = (t & 31) * 4;
            *(float4*)&As[ar][ac] = *(const float4*)(Ag + (size_t)(k0 + ar) * lda + ac);
        }
        if (BTRANS) {
            int br = t >> 1, bk = (t & 1) * 4;
            float4 v = *(const float4*)(Bg + (size_t)br * ldb + k0 + bk);
            Bs[bk + 0][br] = v.x; Bs[bk + 1][br] = v.y;
            Bs[bk + 2][br] = v.z; Bs[bk + 3][br] = v.w;
        } else {
            int br = t >> 5, bc = (t & 31) * 4;
            *(float4*)&Bs[br][bc] = *(const float4*)(Bg + (size_t)(k0 + br) * ldb + bc);
        }
        __syncthreads();
#pragma unroll
        for (int k = 0; k < 8; k++) {
            float a[8], b[8];
            *(float4*)(a)     = *(const float4*)&As[k][row0];
            *(float4*)(a + 4) = *(const float4*)&As[k][row0 + 64];
            *(float4*)(b)     = *(const float4*)&Bs[k][col0];
            *(float4*)(b + 4) = *(const float4*)&Bs[k][col0 + 64];
#pragma unroll
            for (int i = 0; i < 8; i++)
#pragma unroll
                for (int j = 0; j < 8; j++)
                    acc[i][j] += a[i] * b[j];
        }
        __syncthreads();
    }
}

__device__ __forceinline__ int rmap(int i) { return (i < 4) ? i : 60 + i; }

// ---------------------------------------------------------------------------
// QKV = qkv_w(1536x512) @ h(512xT), output channel-major into g_q/g_k/g_v
// ---------------------------------------------------------------------------
__global__ void __launch_bounds__(256, 2) k_qkv(const float* __restrict__ W,
                                                const float* __restrict__ bias) {
    int n  = blockIdx.z;
    int m0 = blockIdx.y * 128;   // d in [0,1536)
    int t0 = blockIdx.x * 128;
    const float* A = W + (size_t)m0 * C;
    const float* B = g_h + (size_t)n * C * T + t0;
    float acc[8][8] = {};
    sgemm_tile<true, false>(A, C, B, T, C, acc);

    int which = m0 / C;
    float* dst = (which == 0 ? g_q : which == 1 ? g_k : g_v) + (size_t)n * C * T;
    int dbase = m0 - which * C;
    const int row0 = (threadIdx.x >> 4) * 4;
    const int col0 = (threadIdx.x & 15) * 4;
#pragma unroll
    for (int i = 0; i < 8; i++) {
        int d = dbase + row0 + rmap(i);
        float bv = bias[m0 + row0 + rmap(i)];
        float4 v0, v1;
        v0.x = acc[i][0] + bv; v0.y = acc[i][1] + bv;
        v0.z = acc[i][2] + bv; v0.w = acc[i][3] + bv;
        v1.x = acc[i][4] + bv; v1.y = acc[i][5] + bv;
        v1.z = acc[i][6] + bv; v1.w = acc[i][7] + bv;
        *(float4*)&dst[(size_t)d * T + t0 + col0]      = v0;
        *(float4*)&dst[(size_t)d * T + t0 + col0 + 64] = v1;
    }
}

// ---------------------------------------------------------------------------
// attn[t][s] = scale * sum_c q[c][t] * k[c][s]   (TN: both operands direct)
// ---------------------------------------------------------------------------
__global__ void __launch_bounds__(256, 2) k_scores() {
    int n  = blockIdx.z;
    int t0 = blockIdx.y * 128;
    int s0 = blockIdx.x * 128;
    const float* A = g_q + (size_t)n * C * T + t0;
    const float* B = g_k + (size_t)n * C * T + s0;
    float acc[8][8] = {};
    sgemm_tile<false, false>(A, T, B, T, C, acc);

    const float scale = 0.04419417382415922f;  // 512^-0.5
    float* dst = g_attn + (size_t)n * T * T;
    const int row0 = (threadIdx.x >> 4) * 4;
    const int col0 = (threadIdx.x & 15) * 4;
#pragma unroll
    for (int i = 0; i < 8; i++) {
        int tt = t0 + row0 + rmap(i);
        float4 v0, v1;
        v0.x = acc[i][0] * scale; v0.y = acc[i][1] * scale;
        v0.z = acc[i][2] * scale; v0.w = acc[i][3] * scale;
        v1.x = acc[i][4] * scale; v1.y = acc[i][5] * scale;
        v1.z = acc[i][6] * scale; v1.w = acc[i][7] * scale;
        *(float4*)&dst[(size_t)tt * T + s0 + col0]      = v0;
        *(float4*)&dst[(size_t)tt * T + s0 + col0 + 64] = v1;
    }
}

// ---------------------------------------------------------------------------
// Row softmax over 4096 elements, whole row in registers (16 floats/thread)
// ---------------------------------------------------------------------------
__global__ void __launch_bounds__(256) k_softmax() {
    float4* p = (float4*)(g_attn + (size_t)blockIdx.x * T);
    const int t = threadIdx.x;
    float4 v[4];
#pragma unroll
    for (int q = 0; q < 4; q++) v[q] = p[t + 256 * q];

    float m = -1e30f;
#pragma unroll
    for (int q = 0; q < 4; q++)
        m = fmaxf(m, fmaxf(fmaxf(v[q].x, v[q].y), fmaxf(v[q].z, v[q].w)));

    __shared__ float red[32];
    int lid = t & 31, wid = t >> 5;
#pragma unroll
    for (int o = 16; o; o >>= 1) m = fmaxf(m, __shfl_xor_sync(0xffffffffu, m, o));
    if (lid == 0) red[wid] = m;
    __syncthreads();
    if (t < 32) {
        m = (t < 8) ? red[t] : -1e30f;
#pragma unroll
        for (int o = 4; o; o >>= 1) m = fmaxf(m, __shfl_xor_sync(0xffffffffu, m, o));
        red[t] = m;
    }
    __syncthreads();
    m = red[0];

    float s = 0.f;
#pragma unroll
    for (int q = 0; q < 4; q++) {
        v[q].x = __expf(v[q].x - m); s += v[q].x;
        v[q].y = __expf(v[q].y - m); s += v[q].y;
        v[q].z = __expf(v[q].z - m); s += v[q].z;
        v[q].w = __expf(v[q].w - m); s += v[q].w;
    }
    __syncthreads();   // protect red reuse
#pragma unroll
    for (int o = 16; o; o >>= 1) s += __shfl_xor_sync(0xffffffffu, s, o);
    if (lid == 0) red[wid] = s;
    __syncthreads();
    if (t < 32) {
        s = (t < 8) ? red[t] : 0.f;
#pragma unroll
        for (int o = 4; o; o >>= 1) s += __shfl_xor_sync(0xffffffffu, s, o);
        red[t] = s;
    }
    __syncthreads();
    float inv = 1.f / red[0];
#pragma unroll
    for (int q = 0; q < 4; q++) {
        v[q].x *= inv; v[q].y *= inv; v[q].z *= inv; v[q].w *= inv;
        p[t + 256 * q] = v[q];
    }
}

// ---------------------------------------------------------------------------
// o[t][c] = sum_s attn[t][s] * v[c][s]   (NT: both transposed into smem)
// ---------------------------------------------------------------------------
__global__ void __launch_bounds__(256, 2) k_av() {
    int n  = blockIdx.z;
    int t0 = blockIdx.y * 128;
    int c0 = blockIdx.x * 128;
    const float* A = g_attn + (size_t)n * T * T + (size_t)t0 * T;
    const float* B = g_v    + (size_t)n * C * T + (size_t)c0 * T;
    float acc[8][8] = {};
    sgemm_tile<true, true>(A, T, B, T, T, acc);

    float* dst = g_o + (size_t)n * T * C;
    const int row0 = (threadIdx.x >> 4) * 4;
    const int col0 = (threadIdx.x & 15) * 4;
#pragma unroll
    for (int i = 0; i < 8; i++) {
        int tt = t0 + row0 + rmap(i);
        float4 v0 = { acc[i][0], acc[i][1], acc[i][2], acc[i][3] };
        float4 v1 = { acc[i][4], acc[i][5], acc[i][6], acc[i][7] };
        *(float4*)&dst[(size_t)tt * C + c0 + col0]      = v0;
        *(float4*)&dst[(size_t)tt * C + c0 + col0 + 64] = v1;
    }
}

// ---------------------------------------------------------------------------
// out[n][d][t] = proj_w[d][:] . o[t][:] + proj_b[d] + x[n][d][t]
// ---------------------------------------------------------------------------
__global__ void __launch_bounds__(256, 2) k_proj(const float* __restrict__ W,
                                                 const float* __restrict__ bias,
                                                 const float* __restrict__ x,
                                                 float* __restrict__ out) {
    int n  = blockIdx.z;
    int d0 = blockIdx.y * 128;
    int t0 = blockIdx.x * 128;
    const float* A = W + (size_t)d0 * C;
    const float* B = g_o + (size_t)n * T * C + (size_t)t0 * C;
    float acc[8][8] = {};
    sgemm_tile<true, true>(A, C, B, C, C, acc);

    const int row0 = (threadIdx.x >> 4) * 4;
    const int col0 = (threadIdx.x & 15) * 4;
#pragma unroll
    for (int i = 0; i < 8; i++) {
        int d = d0 + row0 + rmap(i);
        float bv = bias[d];
        size_t base = ((size_t)n * C + d) * T + t0 + col0;
        float4 x0 = *(const float4*)&x[base];
        float4 x1 = *(const float4*)&x[base + 64];
        float4 v0, v1;
        v0.x = acc[i][0] + bv + x0.x; v0.y = acc[i][1] + bv + x0.y;
        v0.z = acc[i][2] + bv + x0.z; v0.w = acc[i][3] + bv + x0.w;
        v1.x = acc[i][4] + bv + x1.x; v1.y = acc[i][5] + bv + x1.y;
        v1.z = acc[i][6] + bv + x1.z; v1.w = acc[i][7] + bv + x1.w;
        *(float4*)&out[base]      = v0;
        *(float4*)&out[base + 64] = v1;
    }
}

// ---------------------------------------------------------------------------
extern "C" void kernel_launch(void* const* d_in, const int* in_sizes, int n_in,
                              void* d_out, int out_size) {
    const float* x      = (const float*)d_in[0];
    const float* gn_w   = (const float*)d_in[1];
    const float* gn_b   = (const float*)d_in[2];
    const float* qkv_w  = (const float*)d_in[3];
    const float* qkv_b  = (const float*)d_in[4];
    const float* proj_w = (const float*)d_in[5];
    const float* proj_b = (const float*)d_in[6];
    float* out = (float*)d_out;

    gn_kernel<<<NB * GROUPS, 256>>>(x, gn_w, gn_b);
    k_qkv   <<<dim3(T / 128, (3 * C) / 128, NB), 256>>>(qkv_w, qkv_b);
    k_scores<<<dim3(T / 128, T / 128, NB), 256>>>();
    k_softmax<<<NB * T, 256>>>();
    k_av    <<<dim3(C / 128, T / 128, NB), 256>>>();
    k_proj  <<<dim3(T / 128, C / 128, NB), 256>>>(proj_w, proj_b, x, out);
}

// round 3
// speedup vs baseline: 2.4811x; 2.4811x over previous
#include <cuda_runtime.h>
#include <cstdint>

#define NB 8
#define C 512
#define T 4096
#define GROUPS 32
#define CPG (C / GROUPS)      // 16
#define GSZ (CPG * T)         // 65536 elements per group

// Scratch (device globals; no allocations allowed)
__device__ float g_h[(size_t)NB * C * T];        // normalized x, [N][C][T]
__device__ float g_q[(size_t)NB * C * T];        // [N][C][T]
__device__ float g_k[(size_t)NB * C * T];        // [N][C][T]
__device__ float g_v[(size_t)NB * C * T];        // [N][C][T]
__device__ float g_o[(size_t)NB * T * C];        // [N][T][C]
__device__ float g_attn[(size_t)NB * T * T];     // [N][T][T]

// ---------------------------------------------------------------------------
// GroupNorm: one block per (n, group)
// ---------------------------------------------------------------------------
__global__ void __launch_bounds__(256) gn_kernel(const float* __restrict__ x,
                                                 const float* __restrict__ w,
                                                 const float* __restrict__ b) {
    int n = blockIdx.x >> 5;
    int g = blockIdx.x & 31;
    const float4* xp = (const float4*)(x + ((size_t)n * C + g * CPG) * T);
    const int NV = GSZ / 4;

    float s = 0.f, s2 = 0.f;
    for (int i = threadIdx.x; i < NV; i += 256) {
        float4 v = xp[i];
        s  += v.x + v.y + v.z + v.w;
        s2 += v.x * v.x + v.y * v.y + v.z * v.z + v.w * v.w;
    }
    __shared__ float rs[32], rs2[32];
    int lid = threadIdx.x & 31, wid = threadIdx.x >> 5;
#pragma unroll
    for (int o = 16; o; o >>= 1) {
        s  += __shfl_xor_sync(0xffffffffu, s, o);
        s2 += __shfl_xor_sync(0xffffffffu, s2, o);
    }
    if (lid == 0) { rs[wid] = s; rs2[wid] = s2; }
    __syncthreads();
    if (wid == 0) {
        s  = (lid < 8) ? rs[lid]  : 0.f;
        s2 = (lid < 8) ? rs2[lid] : 0.f;
#pragma unroll
        for (int o = 4; o; o >>= 1) {
            s  += __shfl_xor_sync(0xffffffffu, s, o);
            s2 += __shfl_xor_sync(0xffffffffu, s2, o);
        }
        if (lid == 0) { rs[0] = s; rs2[0] = s2; }
    }
    __syncthreads();
    float mean = rs[0] * (1.f / GSZ);
    float var  = rs2[0] * (1.f / GSZ) - mean * mean;
    float inv  = rsqrtf(var + 1e-5f);

    float4* hp = (float4*)(g_h + ((size_t)n * C + g * CPG) * T);
    for (int i = threadIdx.x; i < NV; i += 256) {
        int c = g * CPG + (i >> 10);
        float sc = w[c] * inv;
        float sb = b[c] - mean * sc;
        float4 v = xp[i];
        v.x = v.x * sc + sb;  v.y = v.y * sc + sb;
        v.z = v.z * sc + sb;  v.w = v.w * sc + sb;
        hp[i] = v;
    }
}

// ---------------------------------------------------------------------------
// TF32 tensor-core 128x128 GEMM core (mma.sync.m16n8k8)
//   KC operand  = global layout [X][K] (k-contig)  -> smem [x][k], stride 20
//   KT operand  = global layout [K][X] (x-contig)  -> smem [k][x], stride 136
// Both layouts: float4 STS, conflict-free fragment LDS.
// ---------------------------------------------------------------------------
#define KTILE 16
#define SKC 20     // smem row stride for [x][k] tiles
#define SKT 136    // smem row stride for [k][x] tiles
#define SMW 2560   // words per tile buffer (max(128*20, 16*136))

__device__ __forceinline__ uint32_t f2tf(float f) {
    uint32_t u;
    asm("cvt.rna.tf32.f32 %0, %1;" : "=r"(u) : "f"(f));
    return u;
}

template <bool KC>
__device__ __forceinline__ void ldg_tile(const float* __restrict__ g, int ld,
                                         int k0, int tid, float4 r[2]) {
    if (KC) {
        int x = tid >> 1, kq = (tid & 1) << 3;
        const float* p = g + (size_t)x * ld + k0 + kq;
        r[0] = *(const float4*)p;
        r[1] = *(const float4*)(p + 4);
    } else {
        int k = tid >> 5, x4 = (tid & 31) << 2;
        r[0] = *(const float4*)(g + (size_t)(k0 + k) * ld + x4);
        r[1] = *(const float4*)(g + (size_t)(k0 + k + 8) * ld + x4);
    }
}

template <bool KC>
__device__ __forceinline__ void sts_tile(uint32_t* s, int tid, const float4 r[2]) {
    uint4 u0 = { f2tf(r[0].x), f2tf(r[0].y), f2tf(r[0].z), f2tf(r[0].w) };
    uint4 u1 = { f2tf(r[1].x), f2tf(r[1].y), f2tf(r[1].z), f2tf(r[1].w) };
    if (KC) {
        int x = tid >> 1, kq = (tid & 1) << 3;
        *(uint4*)(s + x * SKC + kq)     = u0;
        *(uint4*)(s + x * SKC + kq + 4) = u1;
    } else {
        int k = tid >> 5, x4 = (tid & 31) << 2;
        *(uint4*)(s + k * SKT + x4)       = u0;
        *(uint4*)(s + (k + 8) * SKT + x4) = u1;
    }
}

template <bool AKC, bool BKC>
__device__ __forceinline__ void gemm128(const float* __restrict__ Ag, int lda,
                                        const float* __restrict__ Bg, int ldb,
                                        int K, float acc[4][4][4]) {
    __shared__ uint32_t sm[2][2][SMW];
    const int tid = threadIdx.x;
    const int warp = tid >> 5, lane = tid & 31;
    const int g = lane >> 2, tg = lane & 3;
    const int mBase = (warp >> 2) * 64;
    const int nBase = (warp & 3) * 32;

    float4 ra[2], rb[2];
    ldg_tile<AKC>(Ag, lda, 0, tid, ra);
    ldg_tile<BKC>(Bg, ldb, 0, tid, rb);
    sts_tile<AKC>(sm[0][0], tid, ra);
    sts_tile<BKC>(sm[0][1], tid, rb);
    __syncthreads();

    const int nk = K >> 4;
    for (int ik = 0; ik < nk; ik++) {
        const int cur = ik & 1;
        if (ik + 1 < nk) {
            ldg_tile<AKC>(Ag, lda, (ik + 1) << 4, tid, ra);
            ldg_tile<BKC>(Bg, ldb, (ik + 1) << 4, tid, rb);
        }
        const uint32_t* As = sm[cur][0];
        const uint32_t* Bs = sm[cur][1];
#pragma unroll
        for (int kk = 0; kk < KTILE; kk += 8) {
            uint32_t a[4][4], b[4][2];
#pragma unroll
            for (int i = 0; i < 4; i++) {
                int m = mBase + i * 16 + g;
                a[i][0] = As[AKC ? m * SKC + kk + tg           : (kk + tg) * SKT + m];
                a[i][1] = As[AKC ? (m + 8) * SKC + kk + tg     : (kk + tg) * SKT + m + 8];
                a[i][2] = As[AKC ? m * SKC + kk + tg + 4       : (kk + tg + 4) * SKT + m];
                a[i][3] = As[AKC ? (m + 8) * SKC + kk + tg + 4 : (kk + tg + 4) * SKT + m + 8];
            }
#pragma unroll
            for (int j = 0; j < 4; j++) {
                int n = nBase + j * 8 + g;
                b[j][0] = Bs[BKC ? n * SKC + kk + tg     : (kk + tg) * SKT + n];
                b[j][1] = Bs[BKC ? n * SKC + kk + tg + 4 : (kk + tg + 4) * SKT + n];
            }
#pragma unroll
            for (int i = 0; i < 4; i++)
#pragma unroll
                for (int j = 0; j < 4; j++)
                    asm("mma.sync.aligned.m16n8k8.row.col.f32.tf32.tf32.f32 "
                        "{%0,%1,%2,%3},{%4,%5,%6,%7},{%8,%9},{%0,%1,%2,%3};"
                        : "+f"(acc[i][j][0]), "+f"(acc[i][j][1]),
                          "+f"(acc[i][j][2]), "+f"(acc[i][j][3])
                        : "r"(a[i][0]), "r"(a[i][1]), "r"(a[i][2]), "r"(a[i][3]),
                          "r"(b[j][0]), "r"(b[j][1]));
        }
        if (ik + 1 < nk) {
            sts_tile<AKC>(sm[cur ^ 1][0], tid, ra);
            sts_tile<BKC>(sm[cur ^ 1][1], tid, rb);
        }
        __syncthreads();
    }
}

// ---------------------------------------------------------------------------
// QKV = qkv_w(1536x512) @ h(512xT), channel-major into g_q/g_k/g_v
// ---------------------------------------------------------------------------
__global__ void __launch_bounds__(256, 2) k_qkv(const float* __restrict__ W,
                                                const float* __restrict__ bias) {
    int n  = blockIdx.z;
    int m0 = blockIdx.y * 128;
    int t0 = blockIdx.x * 128;
    float acc[4][4][4] = {};
    gemm128<true, false>(W + (size_t)m0 * C, C,
                         g_h + (size_t)n * C * T + t0, T, C, acc);

    int which = m0 >> 9;
    float* dst = (which == 0 ? g_q : which == 1 ? g_k : g_v) + (size_t)n * C * T;
    int dbase = m0 & (C - 1);
    const int warp = threadIdx.x >> 5, lane = threadIdx.x & 31;
    const int g = lane >> 2, tg = lane & 3;
    const int mB = (warp >> 2) * 64, nB = (warp & 3) * 32;
#pragma unroll
    for (int i = 0; i < 4; i++) {
        int r = mB + i * 16 + g;
        float bv0 = bias[m0 + r];
        float bv1 = bias[m0 + r + 8];
#pragma unroll
        for (int j = 0; j < 4; j++) {
            int col = t0 + nB + j * 8 + tg * 2;
            float2 v0 = { acc[i][j][0] + bv0, acc[i][j][1] + bv0 };
            float2 v1 = { acc[i][j][2] + bv1, acc[i][j][3] + bv1 };
            *(float2*)&dst[(size_t)(dbase + r) * T + col]     = v0;
            *(float2*)&dst[(size_t)(dbase + r + 8) * T + col] = v1;
        }
    }
}

// ---------------------------------------------------------------------------
// attn[t][s] = scale * sum_c q[c][t] * k[c][s]
// ---------------------------------------------------------------------------
__global__ void __launch_bounds__(256, 2) k_scores() {
    int n  = blockIdx.z;
    int t0 = blockIdx.y * 128;
    int s0 = blockIdx.x * 128;
    float acc[4][4][4] = {};
    gemm128<false, false>(g_q + (size_t)n * C * T + t0, T,
                          g_k + (size_t)n * C * T + s0, T, C, acc);

    const float scale = 0.04419417382415922f;  // 512^-0.5
    float* dst = g_attn + (size_t)n * T * T;
    const int warp = threadIdx.x >> 5, lane = threadIdx.x & 31;
    const int g = lane >> 2, tg = lane & 3;
    const int mB = (warp >> 2) * 64, nB = (warp & 3) * 32;
#pragma unroll
    for (int i = 0; i < 4; i++) {
        int r = t0 + mB + i * 16 + g;
#pragma unroll
        for (int j = 0; j < 4; j++) {
            int col = s0 + nB + j * 8 + tg * 2;
            float2 v0 = { acc[i][j][0] * scale, acc[i][j][1] * scale };
            float2 v1 = { acc[i][j][2] * scale, acc[i][j][3] * scale };
            *(float2*)&dst[(size_t)r * T + col]       = v0;
            *(float2*)&dst[(size_t)(r + 8) * T + col] = v1;
        }
    }
}

// ---------------------------------------------------------------------------
// Row softmax over 4096 elements
// ---------------------------------------------------------------------------
__global__ void __launch_bounds__(256) k_softmax() {
    float4* p = (float4*)(g_attn + (size_t)blockIdx.x * T);
    const int t = threadIdx.x;
    float4 v[4];
#pragma unroll
    for (int q = 0; q < 4; q++) v[q] = p[t + 256 * q];

    float m = -1e30f;
#pragma unroll
    for (int q = 0; q < 4; q++)
        m = fmaxf(m, fmaxf(fmaxf(v[q].x, v[q].y), fmaxf(v[q].z, v[q].w)));

    __shared__ float red[32];
    int lid = t & 31, wid = t >> 5;
#pragma unroll
    for (int o = 16; o; o >>= 1) m = fmaxf(m, __shfl_xor_sync(0xffffffffu, m, o));
    if (lid == 0) red[wid] = m;
    __syncthreads();
    if (t < 32) {
        m = (t < 8) ? red[t] : -1e30f;
#pragma unroll
        for (int o = 4; o; o >>= 1) m = fmaxf(m, __shfl_xor_sync(0xffffffffu, m, o));
        red[t] = m;
    }
    __syncthreads();
    m = red[0];

    float s = 0.f;
#pragma unroll
    for (int q = 0; q < 4; q++) {
        v[q].x = __expf(v[q].x - m); s += v[q].x;
        v[q].y = __expf(v[q].y - m); s += v[q].y;
        v[q].z = __expf(v[q].z - m); s += v[q].z;
        v[q].w = __expf(v[q].w - m); s += v[q].w;
    }
    __syncthreads();
#pragma unroll
    for (int o = 16; o; o >>= 1) s += __shfl_xor_sync(0xffffffffu, s, o);
    if (lid == 0) red[wid] = s;
    __syncthreads();
    if (t < 32) {
        s = (t < 8) ? red[t] : 0.f;
#pragma unroll
        for (int o = 4; o; o >>= 1) s += __shfl_xor_sync(0xffffffffu, s, o);
        red[t] = s;
    }
    __syncthreads();
    float inv = 1.f / red[0];
#pragma unroll
    for (int q = 0; q < 4; q++) {
        v[q].x *= inv; v[q].y *= inv; v[q].z *= inv; v[q].w *= inv;
        p[t + 256 * q] = v[q];
    }
}

// ---------------------------------------------------------------------------
// o[t][c] = sum_s attn[t][s] * v[c][s]
// ---------------------------------------------------------------------------
__global__ void __launch_bounds__(256, 2) k_av() {
    int n  = blockIdx.z;
    int t0 = blockIdx.y * 128;
    int c0 = blockIdx.x * 128;
    float acc[4][4][4] = {};
    gemm128<true, true>(g_attn + (size_t)n * T * T + (size_t)t0 * T, T,
                        g_v    + (size_t)n * C * T + (size_t)c0 * T, T, T, acc);

    float* dst = g_o + (size_t)n * T * C;
    const int warp = threadIdx.x >> 5, lane = threadIdx.x & 31;
    const int g = lane >> 2, tg = lane & 3;
    const int mB = (warp >> 2) * 64, nB = (warp & 3) * 32;
#pragma unroll
    for (int i = 0; i < 4; i++) {
        int r = t0 + mB + i * 16 + g;
#pragma unroll
        for (int j = 0; j < 4; j++) {
            int col = c0 + nB + j * 8 + tg * 2;
            float2 v0 = { acc[i][j][0], acc[i][j][1] };
            float2 v1 = { acc[i][j][2], acc[i][j][3] };
            *(float2*)&dst[(size_t)r * C + col]       = v0;
            *(float2*)&dst[(size_t)(r + 8) * C + col] = v1;
        }
    }
}

// ---------------------------------------------------------------------------
// out[n][d][t] = proj_w[d][:] . o[t][:] + proj_b[d] + x[n][d][t]
// ---------------------------------------------------------------------------
__global__ void __launch_bounds__(256, 2) k_proj(const float* __restrict__ W,
                                                 const float* __restrict__ bias,
                                                 const float* __restrict__ x,
                                                 float* __restrict__ out) {
    int n  = blockIdx.z;
    int d0 = blockIdx.y * 128;
    int t0 = blockIdx.x * 128;
    float acc[4][4][4] = {};
    gemm128<true, true>(W + (size_t)d0 * C, C,
                        g_o + (size_t)t0 * C + (size_t)n * T * C, C, C, acc);

    const int warp = threadIdx.x >> 5, lane = threadIdx.x & 31;
    const int g = lane >> 2, tg = lane & 3;
    const int mB = (warp >> 2) * 64, nB = (warp & 3) * 32;
#pragma unroll
    for (int i = 0; i < 4; i++) {
        int d = d0 + mB + i * 16 + g;
        float bv0 = bias[d];
        float bv1 = bias[d + 8];
#pragma unroll
        for (int j = 0; j < 4; j++) {
            int col = t0 + nB + j * 8 + tg * 2;
            size_t base0 = ((size_t)n * C + d) * T + col;
            size_t base1 = ((size_t)n * C + d + 8) * T + col;
            float2 x0 = *(const float2*)&x[base0];
            float2 x1 = *(const float2*)&x[base1];
            float2 v0 = { acc[i][j][0] + bv0 + x0.x, acc[i][j][1] + bv0 + x0.y };
            float2 v1 = { acc[i][j][2] + bv1 + x1.x, acc[i][j][3] + bv1 + x1.y };
            *(float2*)&out[base0] = v0;
            *(float2*)&out[base1] = v1;
        }
    }
}

// ---------------------------------------------------------------------------
extern "C" void kernel_launch(void* const* d_in, const int* in_sizes, int n_in,
                              void* d_out, int out_size) {
    const float* x      = (const float*)d_in[0];
    const float* gn_w   = (const float*)d_in[1];
    const float* gn_b   = (const float*)d_in[2];
    const float* qkv_w  = (const float*)d_in[3];
    const float* qkv_b  = (const float*)d_in[4];
    const float* proj_w = (const float*)d_in[5];
    const float* proj_b = (const float*)d_in[6];
    float* out = (float*)d_out;

    gn_kernel<<<NB * GROUPS, 256>>>(x, gn_w, gn_b);
    k_qkv   <<<dim3(T / 128, (3 * C) / 128, NB), 256>>>(qkv_w, qkv_b);
    k_scores<<<dim3(T / 128, T / 128, NB), 256>>>();
    k_softmax<<<NB * T, 256>>>();
    k_av    <<<dim3(C / 128, T / 128, NB), 256>>>();
    k_proj  <<<dim3(T / 128, C / 128, NB), 256>>>(proj_w, proj_b, x, out);
}

// round 5
// speedup vs baseline: 3.4083x; 1.3737x over previous
#include <cuda_runtime.h>
#include <cuda_bf16.h>
#include <cstdint>

#define NB 8
#define C 512
#define T 4096
#define GROUPS 32
#define CPG (C / GROUPS)      // 16
#define GSZ (CPG * T)         // 65536 elements per group

// Scratch (device globals; no allocations allowed)
__device__ float g_h[(size_t)NB * C * T];              // normalized x, [N][C][T]
__device__ __nv_bfloat16 g_q[(size_t)NB * C * T];      // [N][C][T]
__device__ __nv_bfloat16 g_k[(size_t)NB * C * T];      // [N][C][T]
__device__ __nv_bfloat16 g_v[(size_t)NB * C * T];      // [N][C][T]
__device__ float g_o[(size_t)NB * T * C];              // [N][T][C]
__device__ float g_attn[(size_t)NB * T * T];           // [N][T][T]

// ---------------------------------------------------------------------------
// GroupNorm: one block per (n, group)
// ---------------------------------------------------------------------------
__global__ void __launch_bounds__(256) gn_kernel(const float* __restrict__ x,
                                                 const float* __restrict__ w,
                                                 const float* __restrict__ b) {
    int n = blockIdx.x >> 5;
    int g = blockIdx.x & 31;
    const float4* xp = (const float4*)(x + ((size_t)n * C + g * CPG) * T);
    const int NV = GSZ / 4;

    float s = 0.f, s2 = 0.f;
    for (int i = threadIdx.x; i < NV; i += 256) {
        float4 v = xp[i];
        s  += v.x + v.y + v.z + v.w;
        s2 += v.x * v.x + v.y * v.y + v.z * v.z + v.w * v.w;
    }
    __shared__ float rs[32], rs2[32];
    int lid = threadIdx.x & 31, wid = threadIdx.x >> 5;
#pragma unroll
    for (int o = 16; o; o >>= 1) {
        s  += __shfl_xor_sync(0xffffffffu, s, o);
        s2 += __shfl_xor_sync(0xffffffffu, s2, o);
    }
    if (lid == 0) { rs[wid] = s; rs2[wid] = s2; }
    __syncthreads();
    if (wid == 0) {
        s  = (lid < 8) ? rs[lid]  : 0.f;
        s2 = (lid < 8) ? rs2[lid] : 0.f;
#pragma unroll
        for (int o = 4; o; o >>= 1) {
            s  += __shfl_xor_sync(0xffffffffu, s, o);
            s2 += __shfl_xor_sync(0xffffffffu, s2, o);
        }
        if (lid == 0) { rs[0] = s; rs2[0] = s2; }
    }
    __syncthreads();
    float mean = rs[0] * (1.f / GSZ);
    float var  = rs2[0] * (1.f / GSZ) - mean * mean;
    float inv  = rsqrtf(var + 1e-5f);

    float4* hp = (float4*)(g_h + ((size_t)n * C + g * CPG) * T);
    for (int i = threadIdx.x; i < NV; i += 256) {
        int c = g * CPG + (i >> 10);
        float sc = w[c] * inv;
        float sb = b[c] - mean * sc;
        float4 v = xp[i];
        v.x = v.x * sc + sb;  v.y = v.y * sc + sb;
        v.z = v.z * sc + sb;  v.w = v.w * sc + sb;
        hp[i] = v;
    }
}

// ===========================================================================
// TF32 tensor-core 128x128 GEMM core (mma.sync.m16n8k8) — for qkv & proj
// ===========================================================================
#define KTILE 16
#define SKC 20
#define SKT 136
#define SMW 2560

__device__ __forceinline__ uint32_t f2tf(float f) {
    uint32_t u;
    asm("cvt.rna.tf32.f32 %0, %1;" : "=r"(u) : "f"(f));
    return u;
}

template <bool KC>
__device__ __forceinline__ void ldg_tile(const float* __restrict__ g, int ld,
                                         int k0, int tid, float4 r[2]) {
    if (KC) {
        int x = tid >> 1, kq = (tid & 1) << 3;
        const float* p = g + (size_t)x * ld + k0 + kq;
        r[0] = *(const float4*)p;
        r[1] = *(const float4*)(p + 4);
    } else {
        int k = tid >> 5, x4 = (tid & 31) << 2;
        r[0] = *(const float4*)(g + (size_t)(k0 + k) * ld + x4);
        r[1] = *(const float4*)(g + (size_t)(k0 + k + 8) * ld + x4);
    }
}

template <bool KC>
__device__ __forceinline__ void sts_tile(uint32_t* s, int tid, const float4 r[2]) {
    uint4 u0 = { f2tf(r[0].x), f2tf(r[0].y), f2tf(r[0].z), f2tf(r[0].w) };
    uint4 u1 = { f2tf(r[1].x), f2tf(r[1].y), f2tf(r[1].z), f2tf(r[1].w) };
    if (KC) {
        int x = tid >> 1, kq = (tid & 1) << 3;
        *(uint4*)(s + x * SKC + kq)     = u0;
        *(uint4*)(s + x * SKC + kq + 4) = u1;
    } else {
        int k = tid >> 5, x4 = (tid & 31) << 2;
        *(uint4*)(s + k * SKT + x4)       = u0;
        *(uint4*)(s + (k + 8) * SKT + x4) = u1;
    }
}

template <bool AKC, bool BKC>
__device__ __forceinline__ void gemm128(const float* __restrict__ Ag, int lda,
                                        const float* __restrict__ Bg, int ldb,
                                        int K, float acc[4][4][4]) {
    __shared__ uint32_t sm[2][2][SMW];
    const int tid = threadIdx.x;
    const int warp = tid >> 5, lane = tid & 31;
    const int g = lane >> 2, tg = lane & 3;
    const int mBase = (warp >> 2) * 64;
    const int nBase = (warp & 3) * 32;

    float4 ra[2], rb[2];
    ldg_tile<AKC>(Ag, lda, 0, tid, ra);
    ldg_tile<BKC>(Bg, ldb, 0, tid, rb);
    sts_tile<AKC>(sm[0][0], tid, ra);
    sts_tile<BKC>(sm[0][1], tid, rb);
    __syncthreads();

    const int nk = K >> 4;
    for (int ik = 0; ik < nk; ik++) {
        const int cur = ik & 1;
        if (ik + 1 < nk) {
            ldg_tile<AKC>(Ag, lda, (ik + 1) << 4, tid, ra);
            ldg_tile<BKC>(Bg, ldb, (ik + 1) << 4, tid, rb);
        }
        const uint32_t* As = sm[cur][0];
        const uint32_t* Bs = sm[cur][1];
#pragma unroll
        for (int kk = 0; kk < KTILE; kk += 8) {
            uint32_t a[4][4], b[4][2];
#pragma unroll
            for (int i = 0; i < 4; i++) {
                int m = mBase + i * 16 + g;
                a[i][0] = As[AKC ? m * SKC + kk + tg           : (kk + tg) * SKT + m];
                a[i][1] = As[AKC ? (m + 8) * SKC + kk + tg     : (kk + tg) * SKT + m + 8];
                a[i][2] = As[AKC ? m * SKC + kk + tg + 4       : (kk + tg + 4) * SKT + m];
                a[i][3] = As[AKC ? (m + 8) * SKC + kk + tg + 4 : (kk + tg + 4) * SKT + m + 8];
            }
#pragma unroll
            for (int j = 0; j < 4; j++) {
                int n = nBase + j * 8 + g;
                b[j][0] = Bs[BKC ? n * SKC + kk + tg     : (kk + tg) * SKT + n];
                b[j][1] = Bs[BKC ? n * SKC + kk + tg + 4 : (kk + tg + 4) * SKT + n];
            }
#pragma unroll
            for (int i = 0; i < 4; i++)
#pragma unroll
                for (int j = 0; j < 4; j++)
                    asm("mma.sync.aligned.m16n8k8.row.col.f32.tf32.tf32.f32 "
                        "{%0,%1,%2,%3},{%4,%5,%6,%7},{%8,%9},{%0,%1,%2,%3};"
                        : "+f"(acc[i][j][0]), "+f"(acc[i][j][1]),
                          "+f"(acc[i][j][2]), "+f"(acc[i][j][3])
                        : "r"(a[i][0]), "r"(a[i][1]), "r"(a[i][2]), "r"(a[i][3]),
                          "r"(b[j][0]), "r"(b[j][1]));
        }
        if (ik + 1 < nk) {
            sts_tile<AKC>(sm[cur ^ 1][0], tid, ra);
            sts_tile<BKC>(sm[cur ^ 1][1], tid, rb);
        }
        __syncthreads();
    }
}

// ===========================================================================
// BF16 tensor-core 128x128 GEMM core (mma.sync.m16n8k16), KTILE = 32
//   MODE 0: KC from bf16 global   ([x][k], k contiguous)
//   MODE 1: KC from fp32 global   (convert at load)
//   MODE 2: KT from bf16 global   ([k][x], x contiguous; interleave k-pairs)
// smem word layouts: KC -> [x][kw], stride 20; KT -> [kw][x], stride 136.
// ===========================================================================
#define BSKC 20
#define BSKT 136
#define BSMW 2560

__device__ __forceinline__ uint32_t packbf(float lo, float hi) {
    __nv_bfloat162 h = __float22bfloat162_rn(make_float2(lo, hi));
    return *(uint32_t*)&h;
}

template <int MODE>
__device__ __forceinline__ void ldg_bf(const void* gp, int ld, int k0, int tid,
                                       uint4 r[2]) {
    if (MODE == 0) {
        const __nv_bfloat16* g = (const __nv_bfloat16*)gp;
        int x = tid >> 1, kq = (tid & 1) << 4;
        const uint4* p = (const uint4*)(g + (size_t)x * ld + k0 + kq);
        r[0] = p[0];
        r[1] = p[1];
    } else if (MODE == 1) {
        const float* g = (const float*)gp;
        int x = tid >> 1, kq = (tid & 1) << 4;
        const float4* p = (const float4*)(g + (size_t)x * ld + k0 + kq);
        float4 f0 = p[0], f1 = p[1], f2 = p[2], f3 = p[3];
        r[0].x = packbf(f0.x, f0.y); r[0].y = packbf(f0.z, f0.w);
        r[0].z = packbf(f1.x, f1.y); r[0].w = packbf(f1.z, f1.w);
        r[1].x = packbf(f2.x, f2.y); r[1].y = packbf(f2.z, f2.w);
        r[1].z = packbf(f3.x, f3.y); r[1].w = packbf(f3.z, f3.w);
    } else {
        const __nv_bfloat16* g = (const __nv_bfloat16*)gp;
        int kw = tid >> 5, x4 = (tid & 31) << 2;
        const __nv_bfloat16* base = g + (size_t)(k0 + 2 * kw) * ld + x4;
        uint2 u0 = *(const uint2*)base;
        uint2 u1 = *(const uint2*)(base + ld);
        uint2 u2 = *(const uint2*)(base + (size_t)16 * ld);
        uint2 u3 = *(const uint2*)(base + (size_t)17 * ld);
        r[0].x = __byte_perm(u0.x, u1.x, 0x5410);
        r[0].y = __byte_perm(u0.x, u1.x, 0x7632);
        r[0].z = __byte_perm(u0.y, u1.y, 0x5410);
        r[0].w = __byte_perm(u0.y, u1.y, 0x7632);
        r[1].x = __byte_perm(u2.x, u3.x, 0x5410);
        r[1].y = __byte_perm(u2.x, u3.x, 0x7632);
        r[1].z = __byte_perm(u2.y, u3.y, 0x5410);
        r[1].w = __byte_perm(u2.y, u3.y, 0x7632);
    }
}

template <int MODE>
__device__ __forceinline__ void sts_bf(uint32_t* s, int tid, const uint4 r[2]) {
    if (MODE == 2) {
        int kw = tid >> 5, x4 = (tid & 31) << 2;
        *(uint4*)(s + kw * BSKT + x4)       = r[0];
        *(uint4*)(s + (kw + 8) * BSKT + x4) = r[1];
    } else {
        int x = tid >> 1, kq8 = (tid & 1) << 3;
        *(uint4*)(s + x * BSKC + kq8)     = r[0];
        *(uint4*)(s + x * BSKC + kq8 + 4) = r[1];
    }
}

template <int AM, int BM>
__device__ __forceinline__ void gemm_bf(const void* Ag, int lda,
                                        const void* Bg, int ldb,
                                        int K, float acc[4][4][4]) {
    __shared__ uint32_t sm[2][2][BSMW];
    const int tid = threadIdx.x;
    const int warp = tid >> 5, lane = tid & 31;
    const int g = lane >> 2, tg = lane & 3;
    const int mBase = (warp >> 2) * 64;
    const int nBase = (warp & 3) * 32;

    uint4 ra[2], rb[2];
    ldg_bf<AM>(Ag, lda, 0, tid, ra);
    ldg_bf<BM>(Bg, ldb, 0, tid, rb);
    sts_bf<AM>(sm[0][0], tid, ra);
    sts_bf<BM>(sm[0][1], tid, rb);
    __syncthreads();

    const int nk = K >> 5;
    for (int ik = 0; ik < nk; ik++) {
        const int cur = ik & 1;
        if (ik + 1 < nk) {
            ldg_bf<AM>(Ag, lda, (ik + 1) << 5, tid, ra);
            ldg_bf<BM>(Bg, ldb, (ik + 1) << 5, tid, rb);
        }
        const uint32_t* As = sm[cur][0];
        const uint32_t* Bs = sm[cur][1];
#pragma unroll
        for (int kks = 0; kks < 2; kks++) {
            const int kw = kks * 8 + tg;
            uint32_t a[4][4], b[4][2];
#pragma unroll
            for (int i = 0; i < 4; i++) {
                int m = mBase + i * 16 + g;
                a[i][0] = As[AM == 2 ? kw * BSKT + m           : m * BSKC + kw];
                a[i][1] = As[AM == 2 ? kw * BSKT + m + 8       : (m + 8) * BSKC + kw];
                a[i][2] = As[AM == 2 ? (kw + 4) * BSKT + m     : m * BSKC + kw + 4];
                a[i][3] = As[AM == 2 ? (kw + 4) * BSKT + m + 8 : (m + 8) * BSKC + kw + 4];
            }
#pragma unroll
            for (int j = 0; j < 4; j++) {
                int n = nBase + j * 8 + g;
                b[j][0] = Bs[BM == 2 ? kw * BSKT + n       : n * BSKC + kw];
                b[j][1] = Bs[BM == 2 ? (kw + 4) * BSKT + n : n * BSKC + kw + 4];
            }
#pragma unroll
            for (int i = 0; i < 4; i++)
#pragma unroll
                for (int j = 0; j < 4; j++)
                    asm("mma.sync.aligned.m16n8k16.row.col.f32.bf16.bf16.f32 "
                        "{%0,%1,%2,%3},{%4,%5,%6,%7},{%8,%9},{%0,%1,%2,%3};"
                        : "+f"(acc[i][j][0]), "+f"(acc[i][j][1]),
                          "+f"(acc[i][j][2]), "+f"(acc[i][j][3])
                        : "r"(a[i][0]), "r"(a[i][1]), "r"(a[i][2]), "r"(a[i][3]),
                          "r"(b[j][0]), "r"(b[j][1]));
        }
        if (ik + 1 < nk) {
            sts_bf<AM>(sm[cur ^ 1][0], tid, ra);
            sts_bf<BM>(sm[cur ^ 1][1], tid, rb);
        }
        __syncthreads();
    }
}

// ---------------------------------------------------------------------------
// QKV = qkv_w(1536x512) @ h(512xT) [tf32], writes bf16 q/k/v channel-major
// ---------------------------------------------------------------------------
__global__ void __launch_bounds__(256, 2) k_qkv(const float* __restrict__ W,
                                                const float* __restrict__ bias) {
    int n  = blockIdx.z;
    int m0 = blockIdx.y * 128;
    int t0 = blockIdx.x * 128;
    float acc[4][4][4] = {};
    gemm128<true, false>(W + (size_t)m0 * C, C,
                         g_h + (size_t)n * C * T + t0, T, C, acc);

    int which = m0 >> 9;
    __nv_bfloat16* dst =
        (which == 0 ? g_q : which == 1 ? g_k : g_v) + (size_t)n * C * T;
    int dbase = m0 & (C - 1);
    const int warp = threadIdx.x >> 5, lane = threadIdx.x & 31;
    const int g = lane >> 2, tg = lane & 3;
    const int mB = (warp >> 2) * 64, nB = (warp & 3) * 32;
#pragma unroll
    for (int i = 0; i < 4; i++) {
        int r = mB + i * 16 + g;
        float bv0 = bias[m0 + r];
        float bv1 = bias[m0 + r + 8];
#pragma unroll
        for (int j = 0; j < 4; j++) {
            int col = t0 + nB + j * 8 + tg * 2;
            uint32_t w0 = packbf(acc[i][j][0] + bv0, acc[i][j][1] + bv0);
            uint32_t w1 = packbf(acc[i][j][2] + bv1, acc[i][j][3] + bv1);
            *(uint32_t*)&dst[(size_t)(dbase + r) * T + col]     = w0;
            *(uint32_t*)&dst[(size_t)(dbase + r + 8) * T + col] = w1;
        }
    }
}

// ---------------------------------------------------------------------------
// attn[t][s] = scale * sum_c q[c][t] * k[c][s]   [bf16 KT x KT]
// ---------------------------------------------------------------------------
__global__ void __launch_bounds__(256, 2) k_scores() {
    int n  = blockIdx.z;
    int t0 = blockIdx.y * 128;
    int s0 = blockIdx.x * 128;
    float acc[4][4][4] = {};
    gemm_bf<2, 2>(g_q + (size_t)n * C * T + t0, T,
                  g_k + (size_t)n * C * T + s0, T, C, acc);

    const float scale = 0.04419417382415922f;  // 512^-0.5
    float* dst = g_attn + (size_t)n * T * T;
    const int warp = threadIdx.x >> 5, lane = threadIdx.x & 31;
    const int g = lane >> 2, tg = lane & 3;
    const int mB = (warp >> 2) * 64, nB = (warp & 3) * 32;
#pragma unroll
    for (int i = 0; i < 4; i++) {
        int r = t0 + mB + i * 16 + g;
#pragma unroll
        for (int j = 0; j < 4; j++) {
            int col = s0 + nB + j * 8 + tg * 2;
            float2 v0 = { acc[i][j][0] * scale, acc[i][j][1] * scale };
            float2 v1 = { acc[i][j][2] * scale, acc[i][j][3] * scale };
            *(float2*)&dst[(size_t)r * T + col]       = v0;
            *(float2*)&dst[(size_t)(r + 8) * T + col] = v1;
        }
    }
}

// ---------------------------------------------------------------------------
// Row softmax over 4096 elements
// ---------------------------------------------------------------------------
__global__ void __launch_bounds__(256) k_softmax() {
    float4* p = (float4*)(g_attn + (size_t)blockIdx.x * T);
    const int t = threadIdx.x;
    float4 v[4];
#pragma unroll
    for (int q = 0; q < 4; q++) v[q] = p[t + 256 * q];

    float m = -1e30f;
#pragma unroll
    for (int q = 0; q < 4; q++)
        m = fmaxf(m, fmaxf(fmaxf(v[q].x, v[q].y), fmaxf(v[q].z, v[q].w)));

    __shared__ float red[32];
    int lid = t & 31, wid = t >> 5;
#pragma unroll
    for (int o = 16; o; o >>= 1) m = fmaxf(m, __shfl_xor_sync(0xffffffffu, m, o));
    if (lid == 0) red[wid] = m;
    __syncthreads();
    if (t < 32) {
        m = (t < 8) ? red[t] : -1e30f;
#pragma unroll
        for (int o = 4; o; o >>= 1) m = fmaxf(m, __shfl_xor_sync(0xffffffffu, m, o));
        red[t] = m;
    }
    __syncthreads();
    m = red[0];

    float s = 0.f;
#pragma unroll
    for (int q = 0; q < 4; q++) {
        v[q].x = __expf(v[q].x - m); s += v[q].x;
        v[q].y = __expf(v[q].y - m); s += v[q].y;
        v[q].z = __expf(v[q].z - m); s += v[q].z;
        v[q].w = __expf(v[q].w - m); s += v[q].w;
    }
    __syncthreads();
#pragma unroll
    for (int o = 16; o; o >>= 1) s += __shfl_xor_sync(0xffffffffu, s, o);
    if (lid == 0) red[wid] = s;
    __syncthreads();
    if (t < 32) {
        s = (t < 8) ? red[t] : 0.f;
#pragma unroll
        for (int o = 4; o; o >>= 1) s += __shfl_xor_sync(0xffffffffu, s, o);
        red[t] = s;
    }
    __syncthreads();
    float inv = 1.f / red[0];
#pragma unroll
    for (int q = 0; q < 4; q++) {
        v[q].x *= inv; v[q].y *= inv; v[q].z *= inv; v[q].w *= inv;
        p[t + 256 * q] = v[q];
    }
}

// ---------------------------------------------------------------------------
// o[t][c] = sum_s attn[t][s] * v[c][s]   [bf16: A=f32 attn KC, B=bf16 v KC]
// ---------------------------------------------------------------------------
__global__ void __launch_bounds__(256, 2) k_av() {
    int n  = blockIdx.z;
    int t0 = blockIdx.y * 128;
    int c0 = blockIdx.x * 128;
    float acc[4][4][4] = {};
    gemm_bf<1, 0>(g_attn + (size_t)n * T * T + (size_t)t0 * T, T,
                  g_v    + (size_t)n * C * T + (size_t)c0 * T, T, T, acc);

    float* dst = g_o + (size_t)n * T * C;
    const int warp = threadIdx.x >> 5, lane = threadIdx.x & 31;
    const int g = lane >> 2, tg = lane & 3;
    const int mB = (warp >> 2) * 64, nB = (warp & 3) * 32;
#pragma unroll
    for (int i = 0; i < 4; i++) {
        int r = t0 + mB + i * 16 + g;
#pragma unroll
        for (int j = 0; j < 4; j++) {
            int col = c0 + nB + j * 8 + tg * 2;
            float2 v0 = { acc[i][j][0], acc[i][j][1] };
            float2 v1 = { acc[i][j][2], acc[i][j][3] };
            *(float2*)&dst[(size_t)r * C + col]       = v0;
            *(float2*)&dst[(size_t)(r + 8) * C + col] = v1;
        }
    }
}

// ---------------------------------------------------------------------------
// out[n][d][t] = proj_w[d][:] . o[t][:] + proj_b[d] + x[n][d][t]  [tf32]
// ---------------------------------------------------------------------------
__global__ void __launch_bounds__(256, 2) k_proj(const float* __restrict__ W,
                                                 const float* __restrict__ bias,
                                                 const float* __restrict__ x,
                                                 float* __restrict__ out) {
    int n  = blockIdx.z;
    int d0 = blockIdx.y * 128;
    int t0 = blockIdx.x * 128;
    float acc[4][4][4] = {};
    gemm128<true, true>(W + (size_t)d0 * C, C,
                        g_o + (size_t)n * T * C + (size_t)t0 * C, C, C, acc);

    const int warp = threadIdx.x >> 5, lane = threadIdx.x & 31;
    const int g = lane >> 2, tg = lane & 3;
    const int mB = (warp >> 2) * 64, nB = (warp & 3) * 32;
#pragma unroll
    for (int i = 0; i < 4; i++) {
        int d = d0 + mB + i * 16 + g;
        float bv0 = bias[d];
        float bv1 = bias[d + 8];
#pragma unroll
        for (int j = 0; j < 4; j++) {
            int col = t0 + nB + j * 8 + tg * 2;
            size_t base0 = ((size_t)n * C + d) * T + col;
            size_t base1 = ((size_t)n * C + d + 8) * T + col;
            float2 x0 = *(const float2*)&x[base0];
            float2 x1 = *(const float2*)&x[base1];
            float2 v0 = { acc[i][j][0] + bv0 + x0.x, acc[i][j][1] + bv0 + x0.y };
            float2 v1 = { acc[i][j][2] + bv1 + x1.x, acc[i][j][3] + bv1 + x1.y };
            *(float2*)&out[base0] = v0;
            *(float2*)&out[base1] = v1;
        }
    }
}

// ---------------------------------------------------------------------------
extern "C" void kernel_launch(void* const* d_in, const int* in_sizes, int n_in,
                              void* d_out, int out_size) {
    const float* x      = (const float*)d_in[0];
    const float* gn_w   = (const float*)d_in[1];
    const float* gn_b   = (const float*)d_in[2];
    const float* qkv_w  = (const float*)d_in[3];
    const float* qkv_b  = (const float*)d_in[4];
    const float* proj_w = (const float*)d_in[5];
    const float* proj_b = (const float*)d_in[6];
    float* out = (float*)d_out;

    gn_kernel<<<NB * GROUPS, 256>>>(x, gn_w, gn_b);
    k_qkv   <<<dim3(T / 128, (3 * C) / 128, NB), 256>>>(qkv_w, qkv_b);
    k_scores<<<dim3(T / 128, T / 128, NB), 256>>>();
    k_softmax<<<NB * T, 256>>>();
    k_av    <<<dim3(C / 128, T / 128, NB), 256>>>();
    k_proj  <<<dim3(T / 128, C / 128, NB), 256>>>(proj_w, proj_b, x, out);
}

// round 6
// speedup vs baseline: 4.4387x; 1.3023x over previous
#include <cuda_runtime.h>
#include <cuda_bf16.h>
#include <cstdint>

#define NB 8
#define C 512
#define T 4096
#define GROUPS 32
#define CPG (C / GROUPS)      // 16
#define GSZ (CPG * T)         // 65536 elements per group

// Scratch (device globals; no allocations allowed)
__device__ float g_sc[NB * C];                         // GN scale  per (n,c)
__device__ float g_sb[NB * C];                         // GN shift  per (n,c)
__device__ __nv_bfloat16 g_q[(size_t)NB * C * T];      // [N][C][T]
__device__ __nv_bfloat16 g_k[(size_t)NB * C * T];      // [N][C][T]
__device__ __nv_bfloat16 g_v[(size_t)NB * C * T];      // [N][C][T]
__device__ __nv_bfloat16 g_o[(size_t)NB * T * C];      // [N][T][C]
__device__ float g_attn[(size_t)NB * T * T];           // [N][T][T] fp32 scores
__device__ __nv_bfloat16 g_p[(size_t)NB * T * T];      // [N][T][T] bf16 probs

// ---------------------------------------------------------------------------
// GroupNorm stats: one block per (n, group); writes per-channel scale/shift
// ---------------------------------------------------------------------------
__global__ void __launch_bounds__(256) gn_stats(const float* __restrict__ x,
                                                const float* __restrict__ w,
                                                const float* __restrict__ b) {
    int n = blockIdx.x >> 5;
    int g = blockIdx.x & 31;
    const float4* xp = (const float4*)(x + ((size_t)n * C + g * CPG) * T);
    const int NV = GSZ / 4;

    float s = 0.f, s2 = 0.f;
    for (int i = threadIdx.x; i < NV; i += 256) {
        float4 v = xp[i];
        s  += v.x + v.y + v.z + v.w;
        s2 += v.x * v.x + v.y * v.y + v.z * v.z + v.w * v.w;
    }
    __shared__ float rs[32], rs2[32];
    int lid = threadIdx.x & 31, wid = threadIdx.x >> 5;
#pragma unroll
    for (int o = 16; o; o >>= 1) {
        s  += __shfl_xor_sync(0xffffffffu, s, o);
        s2 += __shfl_xor_sync(0xffffffffu, s2, o);
    }
    if (lid == 0) { rs[wid] = s; rs2[wid] = s2; }
    __syncthreads();
    if (wid == 0) {
        s  = (lid < 8) ? rs[lid]  : 0.f;
        s2 = (lid < 8) ? rs2[lid] : 0.f;
#pragma unroll
        for (int o = 4; o; o >>= 1) {
            s  += __shfl_xor_sync(0xffffffffu, s, o);
            s2 += __shfl_xor_sync(0xffffffffu, s2, o);
        }
        if (lid == 0) { rs[0] = s; rs2[0] = s2; }
    }
    __syncthreads();
    float mean = rs[0] * (1.f / GSZ);
    float var  = rs2[0] * (1.f / GSZ) - mean * mean;
    float inv  = rsqrtf(var + 1e-5f);

    if (threadIdx.x < CPG) {
        int c = g * CPG + threadIdx.x;
        float scv = w[c] * inv;
        g_sc[n * C + c] = scv;
        g_sb[n * C + c] = b[c] - mean * scv;
    }
}

// ===========================================================================
// BF16 tensor-core 128x128 GEMM core (mma.sync.m16n8k16), KTILE = 32
//   MODE 0: KC from bf16 global   ([x][k], k contiguous)
//   MODE 1: KC from fp32 global   (convert at load)
//   MODE 2: KT from bf16 global   ([k][x]; interleave k-pairs)
//   MODE 3: KT from fp32 global + per-k affine (GroupNorm fused) + convert
// smem word layouts: KC -> [x][kw], stride 20; KT -> [kw][x], stride 136.
// ===========================================================================
#define BSKC 20
#define BSKT 136
#define BSMW 2560

__device__ __forceinline__ uint32_t packbf(float lo, float hi) {
    __nv_bfloat162 h = __float22bfloat162_rn(make_float2(lo, hi));
    return *(uint32_t*)&h;
}

template <int MODE>
__device__ __forceinline__ void ldg_bf(const void* gp, int ld, int k0, int tid,
                                       uint4 r[2],
                                       const float* __restrict__ sc,
                                       const float* __restrict__ sb) {
    if (MODE == 0) {
        const __nv_bfloat16* g = (const __nv_bfloat16*)gp;
        int x = tid >> 1, kq = (tid & 1) << 4;
        const uint4* p = (const uint4*)(g + (size_t)x * ld + k0 + kq);
        r[0] = p[0];
        r[1] = p[1];
    } else if (MODE == 1) {
        const float* g = (const float*)gp;
        int x = tid >> 1, kq = (tid & 1) << 4;
        const float4* p = (const float4*)(g + (size_t)x * ld + k0 + kq);
        float4 f0 = p[0], f1 = p[1], f2 = p[2], f3 = p[3];
        r[0].x = packbf(f0.x, f0.y); r[0].y = packbf(f0.z, f0.w);
        r[0].z = packbf(f1.x, f1.y); r[0].w = packbf(f1.z, f1.w);
        r[1].x = packbf(f2.x, f2.y); r[1].y = packbf(f2.z, f2.w);
        r[1].z = packbf(f3.x, f3.y); r[1].w = packbf(f3.z, f3.w);
    } else if (MODE == 2) {
        const __nv_bfloat16* g = (const __nv_bfloat16*)gp;
        int kw = tid >> 5, x4 = (tid & 31) << 2;
        const __nv_bfloat16* base = g + (size_t)(k0 + 2 * kw) * ld + x4;
        uint2 u0 = *(const uint2*)base;
        uint2 u1 = *(const uint2*)(base + ld);
        uint2 u2 = *(const uint2*)(base + (size_t)16 * ld);
        uint2 u3 = *(const uint2*)(base + (size_t)17 * ld);
        r[0].x = __byte_perm(u0.x, u1.x, 0x5410);
        r[0].y = __byte_perm(u0.x, u1.x, 0x7632);
        r[0].z = __byte_perm(u0.y, u1.y, 0x5410);
        r[0].w = __byte_perm(u0.y, u1.y, 0x7632);
        r[1].x = __byte_perm(u2.x, u3.x, 0x5410);
        r[1].y = __byte_perm(u2.x, u3.x, 0x7632);
        r[1].z = __byte_perm(u2.y, u3.y, 0x5410);
        r[1].w = __byte_perm(u2.y, u3.y, 0x7632);
    } else {
        const float* g = (const float*)gp;
        int kw = tid >> 5, x4 = (tid & 31) << 2;
        int kr = k0 + 2 * kw;
        const float* base = g + (size_t)kr * ld + x4;
        float4 f0 = *(const float4*)base;
        float4 f1 = *(const float4*)(base + ld);
        float4 f2 = *(const float4*)(base + (size_t)16 * ld);
        float4 f3 = *(const float4*)(base + (size_t)17 * ld);
        float s0 = sc[kr],      o0 = sb[kr];
        float s1 = sc[kr + 1],  o1 = sb[kr + 1];
        float s2 = sc[kr + 16], o2 = sb[kr + 16];
        float s3 = sc[kr + 17], o3 = sb[kr + 17];
        r[0].x = packbf(f0.x * s0 + o0, f1.x * s1 + o1);
        r[0].y = packbf(f0.y * s0 + o0, f1.y * s1 + o1);
        r[0].z = packbf(f0.z * s0 + o0, f1.z * s1 + o1);
        r[0].w = packbf(f0.w * s0 + o0, f1.w * s1 + o1);
        r[1].x = packbf(f2.x * s2 + o2, f3.x * s3 + o3);
        r[1].y = packbf(f2.y * s2 + o2, f3.y * s3 + o3);
        r[1].z = packbf(f2.z * s2 + o2, f3.z * s3 + o3);
        r[1].w = packbf(f2.w * s2 + o2, f3.w * s3 + o3);
    }
}

template <int MODE>
__device__ __forceinline__ void sts_bf(uint32_t* s, int tid, const uint4 r[2]) {
    if (MODE == 2 || MODE == 3) {
        int kw = tid >> 5, x4 = (tid & 31) << 2;
        *(uint4*)(s + kw * BSKT + x4)       = r[0];
        *(uint4*)(s + (kw + 8) * BSKT + x4) = r[1];
    } else {
        int x = tid >> 1, kq8 = (tid & 1) << 3;
        *(uint4*)(s + x * BSKC + kq8)     = r[0];
        *(uint4*)(s + x * BSKC + kq8 + 4) = r[1];
    }
}

template <int AM, int BM>
__device__ __forceinline__ void gemm_bf(const void* Ag, int lda,
                                        const void* Bg, int ldb,
                                        int K, float acc[4][4][4],
                                        const float* bsc = nullptr,
                                        const float* bsb = nullptr) {
    __shared__ uint32_t sm[2][2][BSMW];
    const int tid = threadIdx.x;
    const int warp = tid >> 5, lane = tid & 31;
    const int g = lane >> 2, tg = lane & 3;
    const int mBase = (warp >> 2) * 64;
    const int nBase = (warp & 3) * 32;

    uint4 ra[2], rb[2];
    ldg_bf<AM>(Ag, lda, 0, tid, ra, nullptr, nullptr);
    ldg_bf<BM>(Bg, ldb, 0, tid, rb, bsc, bsb);
    sts_bf<AM>(sm[0][0], tid, ra);
    sts_bf<BM>(sm[0][1], tid, rb);
    __syncthreads();

    const int nk = K >> 5;
    for (int ik = 0; ik < nk; ik++) {
        const int cur = ik & 1;
        if (ik + 1 < nk) {
            ldg_bf<AM>(Ag, lda, (ik + 1) << 5, tid, ra, nullptr, nullptr);
            ldg_bf<BM>(Bg, ldb, (ik + 1) << 5, tid, rb, bsc, bsb);
        }
        const uint32_t* As = sm[cur][0];
        const uint32_t* Bs = sm[cur][1];
#pragma unroll
        for (int kks = 0; kks < 2; kks++) {
            const int kw = kks * 8 + tg;
            uint32_t a[4][4], b[4][2];
#pragma unroll
            for (int i = 0; i < 4; i++) {
                int m = mBase + i * 16 + g;
                a[i][0] = As[AM >= 2 ? kw * BSKT + m           : m * BSKC + kw];
                a[i][1] = As[AM >= 2 ? kw * BSKT + m + 8       : (m + 8) * BSKC + kw];
                a[i][2] = As[AM >= 2 ? (kw + 4) * BSKT + m     : m * BSKC + kw + 4];
                a[i][3] = As[AM >= 2 ? (kw + 4) * BSKT + m + 8 : (m + 8) * BSKC + kw + 4];
            }
#pragma unroll
            for (int j = 0; j < 4; j++) {
                int n = nBase + j * 8 + g;
                b[j][0] = Bs[BM >= 2 ? kw * BSKT + n       : n * BSKC + kw];
                b[j][1] = Bs[BM >= 2 ? (kw + 4) * BSKT + n : n * BSKC + kw + 4];
            }
#pragma unroll
            for (int i = 0; i < 4; i++)
#pragma unroll
                for (int j = 0; j < 4; j++)
                    asm("mma.sync.aligned.m16n8k16.row.col.f32.bf16.bf16.f32 "
                        "{%0,%1,%2,%3},{%4,%5,%6,%7},{%8,%9},{%0,%1,%2,%3};"
                        : "+f"(acc[i][j][0]), "+f"(acc[i][j][1]),
                          "+f"(acc[i][j][2]), "+f"(acc[i][j][3])
                        : "r"(a[i][0]), "r"(a[i][1]), "r"(a[i][2]), "r"(a[i][3]),
                          "r"(b[j][0]), "r"(b[j][1]));
        }
        if (ik + 1 < nk) {
            sts_bf<AM>(sm[cur ^ 1][0], tid, ra);
            sts_bf<BM>(sm[cur ^ 1][1], tid, rb);
        }
        __syncthreads();
    }
}

// ---------------------------------------------------------------------------
// QKV = qkv_w(1536x512) @ gn(x)(512xT)  [bf16, GN fused into B load]
// ---------------------------------------------------------------------------
__global__ void __launch_bounds__(256, 2) k_qkv(const float* __restrict__ W,
                                                const float* __restrict__ bias,
                                                const float* __restrict__ x) {
    int n  = blockIdx.z;
    int m0 = blockIdx.y * 128;
    int t0 = blockIdx.x * 128;
    float acc[4][4][4] = {};
    gemm_bf<1, 3>(W + (size_t)m0 * C, C,
                  x + (size_t)n * C * T + t0, T, C, acc,
                  g_sc + n * C, g_sb + n * C);

    int which = m0 >> 9;
    __nv_bfloat16* dst =
        (which == 0 ? g_q : which == 1 ? g_k : g_v) + (size_t)n * C * T;
    int dbase = m0 & (C - 1);
    const int warp = threadIdx.x >> 5, lane = threadIdx.x & 31;
    const int g = lane >> 2, tg = lane & 3;
    const int mB = (warp >> 2) * 64, nB = (warp & 3) * 32;
#pragma unroll
    for (int i = 0; i < 4; i++) {
        int r = mB + i * 16 + g;
        float bv0 = bias[m0 + r];
        float bv1 = bias[m0 + r + 8];
#pragma unroll
        for (int j = 0; j < 4; j++) {
            int col = t0 + nB + j * 8 + tg * 2;
            uint32_t w0 = packbf(acc[i][j][0] + bv0, acc[i][j][1] + bv0);
            uint32_t w1 = packbf(acc[i][j][2] + bv1, acc[i][j][3] + bv1);
            *(uint32_t*)&dst[(size_t)(dbase + r) * T + col]     = w0;
            *(uint32_t*)&dst[(size_t)(dbase + r + 8) * T + col] = w1;
        }
    }
}

// ---------------------------------------------------------------------------
// attn[t][s] = scale * sum_c q[c][t] * k[c][s]   [bf16 KT x KT]
// ---------------------------------------------------------------------------
__global__ void __launch_bounds__(256, 2) k_scores() {
    int n  = blockIdx.z;
    int t0 = blockIdx.y * 128;
    int s0 = blockIdx.x * 128;
    float acc[4][4][4] = {};
    gemm_bf<2, 2>(g_q + (size_t)n * C * T + t0, T,
                  g_k + (size_t)n * C * T + s0, T, C, acc);

    const float scale = 0.04419417382415922f;  // 512^-0.5
    float* dst = g_attn + (size_t)n * T * T;
    const int warp = threadIdx.x >> 5, lane = threadIdx.x & 31;
    const int g = lane >> 2, tg = lane & 3;
    const int mB = (warp >> 2) * 64, nB = (warp & 3) * 32;
#pragma unroll
    for (int i = 0; i < 4; i++) {
        int r = t0 + mB + i * 16 + g;
#pragma unroll
        for (int j = 0; j < 4; j++) {
            int col = s0 + nB + j * 8 + tg * 2;
            float2 v0 = { acc[i][j][0] * scale, acc[i][j][1] * scale };
            float2 v1 = { acc[i][j][2] * scale, acc[i][j][3] * scale };
            *(float2*)&dst[(size_t)r * T + col]       = v0;
            *(float2*)&dst[(size_t)(r + 8) * T + col] = v1;
        }
    }
}

// ---------------------------------------------------------------------------
// Row softmax over 4096 fp32 scores -> bf16 probs
// ---------------------------------------------------------------------------
__global__ void __launch_bounds__(256) k_softmax() {
    const float4* p = (const float4*)(g_attn + (size_t)blockIdx.x * T);
    uint2* po = (uint2*)(g_p + (size_t)blockIdx.x * T);
    const int t = threadIdx.x;
    float4 v[4];
#pragma unroll
    for (int q = 0; q < 4; q++) v[q] = p[t + 256 * q];

    float m = -1e30f;
#pragma unroll
    for (int q = 0; q < 4; q++)
        m = fmaxf(m, fmaxf(fmaxf(v[q].x, v[q].y), fmaxf(v[q].z, v[q].w)));

    __shared__ float red[32];
    int lid = t & 31, wid = t >> 5;
#pragma unroll
    for (int o = 16; o; o >>= 1) m = fmaxf(m, __shfl_xor_sync(0xffffffffu, m, o));
    if (lid == 0) red[wid] = m;
    __syncthreads();
    if (t < 32) {
        m = (t < 8) ? red[t] : -1e30f;
#pragma unroll
        for (int o = 4; o; o >>= 1) m = fmaxf(m, __shfl_xor_sync(0xffffffffu, m, o));
        red[t] = m;
    }
    __syncthreads();
    m = red[0];

    float s = 0.f;
#pragma unroll
    for (int q = 0; q < 4; q++) {
        v[q].x = __expf(v[q].x - m); s += v[q].x;
        v[q].y = __expf(v[q].y - m); s += v[q].y;
        v[q].z = __expf(v[q].z - m); s += v[q].z;
        v[q].w = __expf(v[q].w - m); s += v[q].w;
    }
    __syncthreads();
#pragma unroll
    for (int o = 16; o; o >>= 1) s += __shfl_xor_sync(0xffffffffu, s, o);
    if (lid == 0) red[wid] = s;
    __syncthreads();
    if (t < 32) {
        s = (t < 8) ? red[t] : 0.f;
#pragma unroll
        for (int o = 4; o; o >>= 1) s += __shfl_xor_sync(0xffffffffu, s, o);
        red[t] = s;
    }
    __syncthreads();
    float inv = 1.f / red[0];
#pragma unroll
    for (int q = 0; q < 4; q++) {
        uint2 w;
        w.x = packbf(v[q].x * inv, v[q].y * inv);
        w.y = packbf(v[q].z * inv, v[q].w * inv);
        po[t + 256 * q] = w;
    }
}

// ---------------------------------------------------------------------------
// o[t][c] = sum_s p[t][s] * v[c][s]   [bf16 KC x KC] -> bf16 g_o
// ---------------------------------------------------------------------------
__global__ void __launch_bounds__(256, 2) k_av() {
    int n  = blockIdx.z;
    int t0 = blockIdx.y * 128;
    int c0 = blockIdx.x * 128;
    float acc[4][4][4] = {};
    gemm_bf<0, 0>(g_p + (size_t)n * T * T + (size_t)t0 * T, T,
                  g_v + (size_t)n * C * T + (size_t)c0 * T, T, T, acc);

    __nv_bfloat16* dst = g_o + (size_t)n * T * C;
    const int warp = threadIdx.x >> 5, lane = threadIdx.x & 31;
    const int g = lane >> 2, tg = lane & 3;
    const int mB = (warp >> 2) * 64, nB = (warp & 3) * 32;
#pragma unroll
    for (int i = 0; i < 4; i++) {
        int r = t0 + mB + i * 16 + g;
#pragma unroll
        for (int j = 0; j < 4; j++) {
            int col = c0 + nB + j * 8 + tg * 2;
            uint32_t w0 = packbf(acc[i][j][0], acc[i][j][1]);
            uint32_t w1 = packbf(acc[i][j][2], acc[i][j][3]);
            *(uint32_t*)&dst[(size_t)r * C + col]       = w0;
            *(uint32_t*)&dst[(size_t)(r + 8) * C + col] = w1;
        }
    }
}

// ---------------------------------------------------------------------------
// out[n][d][t] = proj_w[d][:] . o[t][:] + proj_b[d] + x[n][d][t]  [bf16]
// ---------------------------------------------------------------------------
__global__ void __launch_bounds__(256, 2) k_proj(const float* __restrict__ W,
                                                 const float* __restrict__ bias,
                                                 const float* __restrict__ x,
                                                 float* __restrict__ out) {
    int n  = blockIdx.z;
    int d0 = blockIdx.y * 128;
    int t0 = blockIdx.x * 128;
    float acc[4][4][4] = {};
    gemm_bf<1, 0>(W + (size_t)d0 * C, C,
                  g_o + (size_t)n * T * C + (size_t)t0 * C, C, C, acc);

    const int warp = threadIdx.x >> 5, lane = threadIdx.x & 31;
    const int g = lane >> 2, tg = lane & 3;
    const int mB = (warp >> 2) * 64, nB = (warp & 3) * 32;
#pragma unroll
    for (int i = 0; i < 4; i++) {
        int d = d0 + mB + i * 16 + g;
        float bv0 = bias[d];
        float bv1 = bias[d + 8];
#pragma unroll
        for (int j = 0; j < 4; j++) {
            int col = t0 + nB + j * 8 + tg * 2;
            size_t base0 = ((size_t)n * C + d) * T + col;
            size_t base1 = ((size_t)n * C + d + 8) * T + col;
            float2 x0 = *(const float2*)&x[base0];
            float2 x1 = *(const float2*)&x[base1];
            float2 v0 = { acc[i][j][0] + bv0 + x0.x, acc[i][j][1] + bv0 + x0.y };
            float2 v1 = { acc[i][j][2] + bv1 + x1.x, acc[i][j][3] + bv1 + x1.y };
            *(float2*)&out[base0] = v0;
            *(float2*)&out[base1] = v1;
        }
    }
}

// ---------------------------------------------------------------------------
extern "C" void kernel_launch(void* const* d_in, const int* in_sizes, int n_in,
                              void* d_out, int out_size) {
    const float* x      = (const float*)d_in[0];
    const float* gn_w   = (const float*)d_in[1];
    const float* gn_b   = (const float*)d_in[2];
    const float* qkv_w  = (const float*)d_in[3];
    const float* qkv_b  = (const float*)d_in[4];
    const float* proj_w = (const float*)d_in[5];
    const float* proj_b = (const float*)d_in[6];
    float* out = (float*)d_out;

    gn_stats<<<NB * GROUPS, 256>>>(x, gn_w, gn_b);
    k_qkv   <<<dim3(T / 128, (3 * C) / 128, NB), 256>>>(qkv_w, qkv_b, x);
    k_scores<<<dim3(T / 128, T / 128, NB), 256>>>();
    k_softmax<<<NB * T, 256>>>();
    k_av    <<<dim3(C / 128, T / 128, NB), 256>>>();
    k_proj  <<<dim3(T / 128, C / 128, NB), 256>>>(proj_w, proj_b, x, out);
}

// round 7
// speedup vs baseline: 4.8421x; 1.0909x over previous
#include <cuda_runtime.h>
#include <cuda_bf16.h>
#include <cstdint>

#define NB 8
#define C 512
#define T 4096
#define GROUPS 32
#define CPG (C / GROUPS)      // 16
#define GSZ (CPG * T)         // 65536 elements per group

// Scratch (device globals; no allocations allowed)
__device__ float g_sc[NB * C];                         // GN scale  per (n,c)
__device__ float g_sb[NB * C];                         // GN shift  per (n,c)
__device__ __nv_bfloat16 g_q[(size_t)NB * C * T];      // [N][C][T]
__device__ __nv_bfloat16 g_k[(size_t)NB * C * T];      // [N][C][T]
__device__ __nv_bfloat16 g_v[(size_t)NB * C * T];      // [N][C][T]
__device__ __nv_bfloat16 g_o[(size_t)NB * T * C];      // [N][T][C]
__device__ float g_attn[(size_t)NB * T * T];           // [N][T][T] fp32 scores
__device__ __nv_bfloat16 g_p[(size_t)NB * T * T];      // [N][T][T] bf16 probs

// ---------------------------------------------------------------------------
// GroupNorm stats: one block per (n, group); writes per-channel scale/shift
// ---------------------------------------------------------------------------
__global__ void __launch_bounds__(256) gn_stats(const float* __restrict__ x,
                                                const float* __restrict__ w,
                                                const float* __restrict__ b) {
    int n = blockIdx.x >> 5;
    int g = blockIdx.x & 31;
    const float4* xp = (const float4*)(x + ((size_t)n * C + g * CPG) * T);
    const int NV = GSZ / 4;

    float s = 0.f, s2 = 0.f;
    for (int i = threadIdx.x; i < NV; i += 256) {
        float4 v = xp[i];
        s  += v.x + v.y + v.z + v.w;
        s2 += v.x * v.x + v.y * v.y + v.z * v.z + v.w * v.w;
    }
    __shared__ float rs[32], rs2[32];
    int lid = threadIdx.x & 31, wid = threadIdx.x >> 5;
#pragma unroll
    for (int o = 16; o; o >>= 1) {
        s  += __shfl_xor_sync(0xffffffffu, s, o);
        s2 += __shfl_xor_sync(0xffffffffu, s2, o);
    }
    if (lid == 0) { rs[wid] = s; rs2[wid] = s2; }
    __syncthreads();
    if (wid == 0) {
        s  = (lid < 8) ? rs[lid]  : 0.f;
        s2 = (lid < 8) ? rs2[lid] : 0.f;
#pragma unroll
        for (int o = 4; o; o >>= 1) {
            s  += __shfl_xor_sync(0xffffffffu, s, o);
            s2 += __shfl_xor_sync(0xffffffffu, s2, o);
        }
        if (lid == 0) { rs[0] = s; rs2[0] = s2; }
    }
    __syncthreads();
    float mean = rs[0] * (1.f / GSZ);
    float var  = rs2[0] * (1.f / GSZ) - mean * mean;
    float inv  = rsqrtf(var + 1e-5f);

    if (threadIdx.x < CPG) {
        int c = g * CPG + threadIdx.x;
        float scv = w[c] * inv;
        g_sc[n * C + c] = scv;
        g_sb[n * C + c] = b[c] - mean * scv;
    }
}

// ===========================================================================
// BF16 tensor-core 128x128 GEMM core (mma.sync.m16n8k16), KTILE = 32
//   MODE 0: KC from bf16 global   ([x][k], k contiguous)  -> smem [x][kw] s20
//   MODE 1: KC from fp32 global   (convert at load)       -> smem [x][kw] s20
//   MODE 2: KT from bf16 global   ([k][x])                -> smem [k][x]  s68
//   MODE 3: KT from fp32 global + GN affine + convert     -> smem [k][x]  s68
// Fragment loads via ldmatrix (non-trans for KC, trans for KT).
// ===========================================================================
#define BSKC 20
#define KTS  68
#define BSMW 2560

__device__ __forceinline__ uint32_t packbf(float lo, float hi) {
    __nv_bfloat162 h = __float22bfloat162_rn(make_float2(lo, hi));
    return *(uint32_t*)&h;
}

__device__ __forceinline__ void ldsm_x4(uint32_t a[4], uint32_t addr) {
    asm volatile("ldmatrix.sync.aligned.m8n8.x4.shared.b16 {%0,%1,%2,%3}, [%4];"
                 : "=r"(a[0]), "=r"(a[1]), "=r"(a[2]), "=r"(a[3]) : "r"(addr));
}
__device__ __forceinline__ void ldsm_x4t(uint32_t a[4], uint32_t addr) {
    asm volatile("ldmatrix.sync.aligned.m8n8.x4.trans.shared.b16 {%0,%1,%2,%3}, [%4];"
                 : "=r"(a[0]), "=r"(a[1]), "=r"(a[2]), "=r"(a[3]) : "r"(addr));
}
__device__ __forceinline__ void ldsm_x2(uint32_t b[2], uint32_t addr) {
    asm volatile("ldmatrix.sync.aligned.m8n8.x2.shared.b16 {%0,%1}, [%2];"
                 : "=r"(b[0]), "=r"(b[1]) : "r"(addr));
}
__device__ __forceinline__ void ldsm_x2t(uint32_t b[2], uint32_t addr) {
    asm volatile("ldmatrix.sync.aligned.m8n8.x2.trans.shared.b16 {%0,%1}, [%2];"
                 : "=r"(b[0]), "=r"(b[1]) : "r"(addr));
}

template <int MODE>
__device__ __forceinline__ void ldg_bf(const void* gp, int ld, int k0, int tid,
                                       uint4 r[2],
                                       const float* __restrict__ sc,
                                       const float* __restrict__ sb) {
    if (MODE == 0) {
        const __nv_bfloat16* g = (const __nv_bfloat16*)gp;
        int x = tid >> 1, kq = (tid & 1) << 4;
        const uint4* p = (const uint4*)(g + (size_t)x * ld + k0 + kq);
        r[0] = p[0];
        r[1] = p[1];
    } else if (MODE == 1) {
        const float* g = (const float*)gp;
        int x = tid >> 1, kq = (tid & 1) << 4;
        const float4* p = (const float4*)(g + (size_t)x * ld + k0 + kq);
        float4 f0 = p[0], f1 = p[1], f2 = p[2], f3 = p[3];
        r[0].x = packbf(f0.x, f0.y); r[0].y = packbf(f0.z, f0.w);
        r[0].z = packbf(f1.x, f1.y); r[0].w = packbf(f1.z, f1.w);
        r[1].x = packbf(f2.x, f2.y); r[1].y = packbf(f2.z, f2.w);
        r[1].z = packbf(f3.x, f3.y); r[1].w = packbf(f3.z, f3.w);
    } else if (MODE == 2) {
        const __nv_bfloat16* g = (const __nv_bfloat16*)gp;
        int kw = tid >> 5, x4 = (tid & 31) << 2;
        const __nv_bfloat16* base = g + (size_t)(k0 + 2 * kw) * ld + x4;
        uint2 u0 = *(const uint2*)base;
        uint2 u1 = *(const uint2*)(base + ld);
        uint2 u2 = *(const uint2*)(base + (size_t)16 * ld);
        uint2 u3 = *(const uint2*)(base + (size_t)17 * ld);
        r[0].x = u0.x; r[0].y = u0.y; r[0].z = u1.x; r[0].w = u1.y;
        r[1].x = u2.x; r[1].y = u2.y; r[1].z = u3.x; r[1].w = u3.y;
    } else {
        const float* g = (const float*)gp;
        int kw = tid >> 5, x4 = (tid & 31) << 2;
        int kr = k0 + 2 * kw;
        const float* base = g + (size_t)kr * ld + x4;
        float4 f0 = *(const float4*)base;
        float4 f1 = *(const float4*)(base + ld);
        float4 f2 = *(const float4*)(base + (size_t)16 * ld);
        float4 f3 = *(const float4*)(base + (size_t)17 * ld);
        float s0 = sc[kr],      o0 = sb[kr];
        float s1 = sc[kr + 1],  o1 = sb[kr + 1];
        float s2 = sc[kr + 16], o2 = sb[kr + 16];
        float s3 = sc[kr + 17], o3 = sb[kr + 17];
        r[0].x = packbf(f0.x * s0 + o0, f0.y * s0 + o0);
        r[0].y = packbf(f0.z * s0 + o0, f0.w * s0 + o0);
        r[0].z = packbf(f1.x * s1 + o1, f1.y * s1 + o1);
        r[0].w = packbf(f1.z * s1 + o1, f1.w * s1 + o1);
        r[1].x = packbf(f2.x * s2 + o2, f2.y * s2 + o2);
        r[1].y = packbf(f2.z * s2 + o2, f2.w * s2 + o2);
        r[1].z = packbf(f3.x * s3 + o3, f3.y * s3 + o3);
        r[1].w = packbf(f3.z * s3 + o3, f3.w * s3 + o3);
    }
}

template <int MODE>
__device__ __forceinline__ void sts_bf(uint32_t* s, int tid, const uint4 r[2]) {
    if (MODE >= 2) {
        int kw = tid >> 5, xw = (tid & 31) * 2;
        *(uint2*)(s + (2 * kw) * KTS + xw)      = make_uint2(r[0].x, r[0].y);
        *(uint2*)(s + (2 * kw + 1) * KTS + xw)  = make_uint2(r[0].z, r[0].w);
        *(uint2*)(s + (2 * kw + 16) * KTS + xw) = make_uint2(r[1].x, r[1].y);
        *(uint2*)(s + (2 * kw + 17) * KTS + xw) = make_uint2(r[1].z, r[1].w);
    } else {
        int x = tid >> 1, kq8 = (tid & 1) << 3;
        *(uint4*)(s + x * BSKC + kq8)     = r[0];
        *(uint4*)(s + x * BSKC + kq8 + 4) = r[1];
    }
}

template <int AM, int BM>
__device__ __forceinline__ void gemm_bf(const void* Ag, int lda,
                                        const void* Bg, int ldb,
                                        int K, float acc[4][4][4],
                                        const float* bsc = nullptr,
                                        const float* bsb = nullptr) {
    __shared__ uint32_t sm[2][2][BSMW];
    const int tid = threadIdx.x;
    const int warp = tid >> 5, lane = tid & 31;
    const int mBase = (warp >> 2) * 64;
    const int nBase = (warp & 3) * 32;
    // ldmatrix lane decomposition
    const int l8 = lane & 7, lb3 = (lane >> 3) & 1, lb4 = (lane >> 4) & 1;
    const int lm = lane & 15, lm8 = lm & 7, lmb3 = (lm >> 3) & 1;

    const uint32_t smAddr = (uint32_t)__cvta_generic_to_shared(&sm[0][0][0]);

    uint4 ra[2], rb[2];
    ldg_bf<AM>(Ag, lda, 0, tid, ra, nullptr, nullptr);
    ldg_bf<BM>(Bg, ldb, 0, tid, rb, bsc, bsb);
    sts_bf<AM>(sm[0][0], tid, ra);
    sts_bf<BM>(sm[0][1], tid, rb);
    __syncthreads();

    const int nk = K >> 5;
    for (int ik = 0; ik < nk; ik++) {
        const int cur = ik & 1;
        if (ik + 1 < nk) {
            ldg_bf<AM>(Ag, lda, (ik + 1) << 5, tid, ra, nullptr, nullptr);
            ldg_bf<BM>(Bg, ldb, (ik + 1) << 5, tid, rb, bsc, bsb);
        }
        const uint32_t baseA = smAddr + (uint32_t)(cur * 2 + 0) * (BSMW * 4);
        const uint32_t baseB = smAddr + (uint32_t)(cur * 2 + 1) * (BSMW * 4);
#pragma unroll
        for (int kks = 0; kks < 2; kks++) {
            uint32_t a[4][4], b[4][2];
#pragma unroll
            for (int i = 0; i < 4; i++) {
                uint32_t ad;
                if (AM < 2)
                    ad = baseA + (uint32_t)(((mBase + i * 16 + l8 + lb3 * 8) * BSKC
                                             + kks * 8 + lb4 * 4) << 2);
                else
                    ad = baseA + (uint32_t)(((kks * 16 + l8 + lb4 * 8) * KTS) << 2)
                               + (uint32_t)((mBase + i * 16 + lb3 * 8) << 1);
                if (AM < 2) ldsm_x4(a[i], ad); else ldsm_x4t(a[i], ad);
            }
#pragma unroll
            for (int j = 0; j < 4; j++) {
                uint32_t bd;
                if (BM < 2)
                    bd = baseB + (uint32_t)(((nBase + j * 8 + lm8) * BSKC
                                             + kks * 8 + lmb3 * 4) << 2);
                else
                    bd = baseB + (uint32_t)(((kks * 16 + lm8 + lmb3 * 8) * KTS) << 2)
                               + (uint32_t)((nBase + j * 8) << 1);
                if (BM < 2) ldsm_x2(b[j], bd); else ldsm_x2t(b[j], bd);
            }
#pragma unroll
            for (int i = 0; i < 4; i++)
#pragma unroll
                for (int j = 0; j < 4; j++)
                    asm("mma.sync.aligned.m16n8k16.row.col.f32.bf16.bf16.f32 "
                        "{%0,%1,%2,%3},{%4,%5,%6,%7},{%8,%9},{%0,%1,%2,%3};"
                        : "+f"(acc[i][j][0]), "+f"(acc[i][j][1]),
                          "+f"(acc[i][j][2]), "+f"(acc[i][j][3])
                        : "r"(a[i][0]), "r"(a[i][1]), "r"(a[i][2]), "r"(a[i][3]),
                          "r"(b[j][0]), "r"(b[j][1]));
        }
        if (ik + 1 < nk) {
            sts_bf<AM>(sm[cur ^ 1][0], tid, ra);
            sts_bf<BM>(sm[cur ^ 1][1], tid, rb);
        }
        __syncthreads();
    }
}

// ---------------------------------------------------------------------------
// QKV = qkv_w(1536x512) @ gn(x)(512xT)  [bf16, GN fused into B load]
// ---------------------------------------------------------------------------
__global__ void __launch_bounds__(256, 2) k_qkv(const float* __restrict__ W,
                                                const float* __restrict__ bias,
                                                const float* __restrict__ x) {
    int n  = blockIdx.z;
    int m0 = blockIdx.y * 128;
    int t0 = blockIdx.x * 128;
    float acc[4][4][4] = {};
    gemm_bf<1, 3>(W + (size_t)m0 * C, C,
                  x + (size_t)n * C * T + t0, T, C, acc,
                  g_sc + n * C, g_sb + n * C);

    int which = m0 >> 9;
    __nv_bfloat16* dst =
        (which == 0 ? g_q : which == 1 ? g_k : g_v) + (size_t)n * C * T;
    int dbase = m0 & (C - 1);
    const int warp = threadIdx.x >> 5, lane = threadIdx.x & 31;
    const int g = lane >> 2, tg = lane & 3;
    const int mB = (warp >> 2) * 64, nB = (warp & 3) * 32;
#pragma unroll
    for (int i = 0; i < 4; i++) {
        int r = mB + i * 16 + g;
        float bv0 = bias[m0 + r];
        float bv1 = bias[m0 + r + 8];
#pragma unroll
        for (int j = 0; j < 4; j++) {
            int col = t0 + nB + j * 8 + tg * 2;
            uint32_t w0 = packbf(acc[i][j][0] + bv0, acc[i][j][1] + bv0);
            uint32_t w1 = packbf(acc[i][j][2] + bv1, acc[i][j][3] + bv1);
            *(uint32_t*)&dst[(size_t)(dbase + r) * T + col]     = w0;
            *(uint32_t*)&dst[(size_t)(dbase + r + 8) * T + col] = w1;
        }
    }
}

// ---------------------------------------------------------------------------
// attn[t][s] = scale * sum_c q[c][t] * k[c][s]   [bf16 KT x KT]
// ---------------------------------------------------------------------------
__global__ void __launch_bounds__(256, 2) k_scores() {
    int n  = blockIdx.z;
    int t0 = blockIdx.y * 128;
    int s0 = blockIdx.x * 128;
    float acc[4][4][4] = {};
    gemm_bf<2, 2>(g_q + (size_t)n * C * T + t0, T,
                  g_k + (size_t)n * C * T + s0, T, C, acc);

    const float scale = 0.04419417382415922f;  // 512^-0.5
    float* dst = g_attn + (size_t)n * T * T;
    const int warp = threadIdx.x >> 5, lane = threadIdx.x & 31;
    const int g = lane >> 2, tg = lane & 3;
    const int mB = (warp >> 2) * 64, nB = (warp & 3) * 32;
#pragma unroll
    for (int i = 0; i < 4; i++) {
        int r = t0 + mB + i * 16 + g;
#pragma unroll
        for (int j = 0; j < 4; j++) {
            int col = s0 + nB + j * 8 + tg * 2;
            float2 v0 = { acc[i][j][0] * scale, acc[i][j][1] * scale };
            float2 v1 = { acc[i][j][2] * scale, acc[i][j][3] * scale };
            *(float2*)&dst[(size_t)r * T + col]       = v0;
            *(float2*)&dst[(size_t)(r + 8) * T + col] = v1;
        }
    }
}

// ---------------------------------------------------------------------------
// Row softmax over 4096 fp32 scores -> bf16 probs
// ---------------------------------------------------------------------------
__global__ void __launch_bounds__(256) k_softmax() {
    const float4* p = (const float4*)(g_attn + (size_t)blockIdx.x * T);
    uint2* po = (uint2*)(g_p + (size_t)blockIdx.x * T);
    const int t = threadIdx.x;
    float4 v[4];
#pragma unroll
    for (int q = 0; q < 4; q++) v[q] = p[t + 256 * q];

    float m = -1e30f;
#pragma unroll
    for (int q = 0; q < 4; q++)
        m = fmaxf(m, fmaxf(fmaxf(v[q].x, v[q].y), fmaxf(v[q].z, v[q].w)));

    __shared__ float red[32];
    int lid = t & 31, wid = t >> 5;
#pragma unroll
    for (int o = 16; o; o >>= 1) m = fmaxf(m, __shfl_xor_sync(0xffffffffu, m, o));
    if (lid == 0) red[wid] = m;
    __syncthreads();
    if (t < 32) {
        m = (t < 8) ? red[t] : -1e30f;
#pragma unroll
        for (int o = 4; o; o >>= 1) m = fmaxf(m, __shfl_xor_sync(0xffffffffu, m, o));
        red[t] = m;
    }
    __syncthreads();
    m = red[0];

    float s = 0.f;
#pragma unroll
    for (int q = 0; q < 4; q++) {
        v[q].x = __expf(v[q].x - m); s += v[q].x;
        v[q].y = __expf(v[q].y - m); s += v[q].y;
        v[q].z = __expf(v[q].z - m); s += v[q].z;
        v[q].w = __expf(v[q].w - m); s += v[q].w;
    }
    __syncthreads();
#pragma unroll
    for (int o = 16; o; o >>= 1) s += __shfl_xor_sync(0xffffffffu, s, o);
    if (lid == 0) red[wid] = s;
    __syncthreads();
    if (t < 32) {
        s = (t < 8) ? red[t] : 0.f;
#pragma unroll
        for (int o = 4; o; o >>= 1) s += __shfl_xor_sync(0xffffffffu, s, o);
        red[t] = s;
    }
    __syncthreads();
    float inv = 1.f / red[0];
#pragma unroll
    for (int q = 0; q < 4; q++) {
        uint2 w;
        w.x = packbf(v[q].x * inv, v[q].y * inv);
        w.y = packbf(v[q].z * inv, v[q].w * inv);
        po[t + 256 * q] = w;
    }
}

// ---------------------------------------------------------------------------
// o[t][c] = sum_s p[t][s] * v[c][s]   [bf16 KC x KC] -> bf16 g_o
// ---------------------------------------------------------------------------
__global__ void __launch_bounds__(256, 2) k_av() {
    int n  = blockIdx.z;
    int t0 = blockIdx.y * 128;
    int c0 = blockIdx.x * 128;
    float acc[4][4][4] = {};
    gemm_bf<0, 0>(g_p + (size_t)n * T * T + (size_t)t0 * T, T,
                  g_v + (size_t)n * C * T + (size_t)c0 * T, T, T, acc);

    __nv_bfloat16* dst = g_o + (size_t)n * T * C;
    const int warp = threadIdx.x >> 5, lane = threadIdx.x & 31;
    const int g = lane >> 2, tg = lane & 3;
    const int mB = (warp >> 2) * 64, nB = (warp & 3) * 32;
#pragma unroll
    for (int i = 0; i < 4; i++) {
        int r = t0 + mB + i * 16 + g;
#pragma unroll
        for (int j = 0; j < 4; j++) {
            int col = c0 + nB + j * 8 + tg * 2;
            uint32_t w0 = packbf(acc[i][j][0], acc[i][j][1]);
            uint32_t w1 = packbf(acc[i][j][2], acc[i][j][3]);
            *(uint32_t*)&dst[(size_t)r * C + col]       = w0;
            *(uint32_t*)&dst[(size_t)(r + 8) * C + col] = w1;
        }
    }
}

// ---------------------------------------------------------------------------
// out[n][d][t] = proj_w[d][:] . o[t][:] + proj_b[d] + x[n][d][t]  [bf16]
// ---------------------------------------------------------------------------
__global__ void __launch_bounds__(256, 2) k_proj(const float* __restrict__ W,
                                                 const float* __restrict__ bias,
                                                 const float* __restrict__ x,
                                                 float* __restrict__ out) {
    int n  = blockIdx.z;
    int d0 = blockIdx.y * 128;
    int t0 = blockIdx.x * 128;
    float acc[4][4][4] = {};
    gemm_bf<1, 0>(W + (size_t)d0 * C, C,
                  g_o + (size_t)n * T * C + (size_t)t0 * C, C, C, acc);

    const int warp = threadIdx.x >> 5, lane = threadIdx.x & 31;
    const int g = lane >> 2, tg = lane & 3;
    const int mB = (warp >> 2) * 64, nB = (warp & 3) * 32;
#pragma unroll
    for (int i = 0; i < 4; i++) {
        int d = d0 + mB + i * 16 + g;
        float bv0 = bias[d];
        float bv1 = bias[d + 8];
#pragma unroll
        for (int j = 0; j < 4; j++) {
            int col = t0 + nB + j * 8 + tg * 2;
            size_t base0 = ((size_t)n * C + d) * T + col;
            size_t base1 = ((size_t)n * C + d + 8) * T + col;
            float2 x0 = *(const float2*)&x[base0];
            float2 x1 = *(const float2*)&x[base1];
            float2 v0 = { acc[i][j][0] + bv0 + x0.x, acc[i][j][1] + bv0 + x0.y };
            float2 v1 = { acc[i][j][2] + bv1 + x1.x, acc[i][j][3] + bv1 + x1.y };
            *(float2*)&out[base0] = v0;
            *(float2*)&out[base1] = v1;
        }
    }
}

// ---------------------------------------------------------------------------
extern "C" void kernel_launch(void* const* d_in, const int* in_sizes, int n_in,
                              void* d_out, int out_size) {
    const float* x      = (const float*)d_in[0];
    const float* gn_w   = (const float*)d_in[1];
    const float* gn_b   = (const float*)d_in[2];
    const float* qkv_w  = (const float*)d_in[3];
    const float* qkv_b  = (const float*)d_in[4];
    const float* proj_w = (const float*)d_in[5];
    const float* proj_b = (const float*)d_in[6];
    float* out = (float*)d_out;

    gn_stats<<<NB * GROUPS, 256>>>(x, gn_w, gn_b);
    k_qkv   <<<dim3(T / 128, (3 * C) / 128, NB), 256>>>(qkv_w, qkv_b, x);
    k_scores<<<dim3(T / 128, T / 128, NB), 256>>>();
    k_softmax<<<NB * T, 256>>>();
    k_av    <<<dim3(C / 128, T / 128, NB), 256>>>();
    k_proj  <<<dim3(T / 128, C / 128, NB), 256>>>(proj_w, proj_b, x, out);
}

// round 8
// speedup vs baseline: 5.1081x; 1.0549x over previous
#include <cuda_runtime.h>
#include <cuda_bf16.h>
#include <cstdint>

#define NB 8
#define C 512
#define T 4096
#define GROUPS 32
#define CPG (C / GROUPS)      // 16
#define GSZ (CPG * T)         // 65536 elements per group

// Scratch (device globals; no allocations allowed)
__device__ float g_sc[NB * C];                         // GN scale  per (n,c)
__device__ float g_sb[NB * C];                         // GN shift  per (n,c)
__device__ __nv_bfloat16 g_q[(size_t)NB * C * T];      // [N][C][T]
__device__ __nv_bfloat16 g_k[(size_t)NB * C * T];      // [N][C][T]
__device__ __nv_bfloat16 g_v[(size_t)NB * C * T];      // [N][C][T]
__device__ __nv_bfloat16 g_o[(size_t)NB * T * C];      // [N][T][C]
__device__ __nv_bfloat16 g_p[(size_t)NB * T * T];      // [N][T][T] bf16 exp(S)
__device__ float g_lp[(size_t)NB * 32 * T];            // partial row sums
__device__ float g_li[NB * T];                         // 1 / row sum

// ---------------------------------------------------------------------------
// GroupNorm stats: one block per (n, group); writes per-channel scale/shift
// ---------------------------------------------------------------------------
__global__ void __launch_bounds__(256) gn_stats(const float* __restrict__ x,
                                                const float* __restrict__ w,
                                                const float* __restrict__ b) {
    int n = blockIdx.x >> 5;
    int g = blockIdx.x & 31;
    const float4* xp = (const float4*)(x + ((size_t)n * C + g * CPG) * T);
    const int NV = GSZ / 4;

    float s = 0.f, s2 = 0.f;
    for (int i = threadIdx.x; i < NV; i += 256) {
        float4 v = xp[i];
        s  += v.x + v.y + v.z + v.w;
        s2 += v.x * v.x + v.y * v.y + v.z * v.z + v.w * v.w;
    }
    __shared__ float rs[32], rs2[32];
    int lid = threadIdx.x & 31, wid = threadIdx.x >> 5;
#pragma unroll
    for (int o = 16; o; o >>= 1) {
        s  += __shfl_xor_sync(0xffffffffu, s, o);
        s2 += __shfl_xor_sync(0xffffffffu, s2, o);
    }
    if (lid == 0) { rs[wid] = s; rs2[wid] = s2; }
    __syncthreads();
    if (wid == 0) {
        s  = (lid < 8) ? rs[lid]  : 0.f;
        s2 = (lid < 8) ? rs2[lid] : 0.f;
#pragma unroll
        for (int o = 4; o; o >>= 1) {
            s  += __shfl_xor_sync(0xffffffffu, s, o);
            s2 += __shfl_xor_sync(0xffffffffu, s2, o);
        }
        if (lid == 0) { rs[0] = s; rs2[0] = s2; }
    }
    __syncthreads();
    float mean = rs[0] * (1.f / GSZ);
    float var  = rs2[0] * (1.f / GSZ) - mean * mean;
    float inv  = rsqrtf(var + 1e-5f);

    if (threadIdx.x < CPG) {
        int c = g * CPG + threadIdx.x;
        float scv = w[c] * inv;
        g_sc[n * C + c] = scv;
        g_sb[n * C + c] = b[c] - mean * scv;
    }
}

// ===========================================================================
// BF16 tensor-core 128x128 GEMM core (mma.sync.m16n8k16), KTILE = 32
//   MODE 0: KC from bf16 global   ([x][k], k contiguous)  -> smem [x][kw] s20
//   MODE 1: KC from fp32 global   (convert at load)       -> smem [x][kw] s20
//   MODE 2: KT from bf16 global   ([k][x])                -> smem [k][x]  s68
//   MODE 3: KT from fp32 global + GN affine + convert     -> smem [k][x]  s68
// Fragment loads via ldmatrix (non-trans for KC, trans for KT).
// ===========================================================================
#define BSKC 20
#define KTS  68
#define BSMW 2560

__device__ __forceinline__ uint32_t packbf(float lo, float hi) {
    __nv_bfloat162 h = __float22bfloat162_rn(make_float2(lo, hi));
    return *(uint32_t*)&h;
}

__device__ __forceinline__ void ldsm_x4(uint32_t a[4], uint32_t addr) {
    asm volatile("ldmatrix.sync.aligned.m8n8.x4.shared.b16 {%0,%1,%2,%3}, [%4];"
                 : "=r"(a[0]), "=r"(a[1]), "=r"(a[2]), "=r"(a[3]) : "r"(addr));
}
__device__ __forceinline__ void ldsm_x4t(uint32_t a[4], uint32_t addr) {
    asm volatile("ldmatrix.sync.aligned.m8n8.x4.trans.shared.b16 {%0,%1,%2,%3}, [%4];"
                 : "=r"(a[0]), "=r"(a[1]), "=r"(a[2]), "=r"(a[3]) : "r"(addr));
}
__device__ __forceinline__ void ldsm_x2(uint32_t b[2], uint32_t addr) {
    asm volatile("ldmatrix.sync.aligned.m8n8.x2.shared.b16 {%0,%1}, [%2];"
                 : "=r"(b[0]), "=r"(b[1]) : "r"(addr));
}
__device__ __forceinline__ void ldsm_x2t(uint32_t b[2], uint32_t addr) {
    asm volatile("ldmatrix.sync.aligned.m8n8.x2.trans.shared.b16 {%0,%1}, [%2];"
                 : "=r"(b[0]), "=r"(b[1]) : "r"(addr));
}

template <int MODE>
__device__ __forceinline__ void ldg_bf(const void* gp, int ld, int k0, int tid,
                                       uint4 r[2],
                                       const float* __restrict__ sc,
                                       const float* __restrict__ sb) {
    if (MODE == 0) {
        const __nv_bfloat16* g = (const __nv_bfloat16*)gp;
        int x = tid >> 1, kq = (tid & 1) << 4;
        const uint4* p = (const uint4*)(g + (size_t)x * ld + k0 + kq);
        r[0] = p[0];
        r[1] = p[1];
    } else if (MODE == 1) {
        const float* g = (const float*)gp;
        int x = tid >> 1, kq = (tid & 1) << 4;
        const float4* p = (const float4*)(g + (size_t)x * ld + k0 + kq);
        float4 f0 = p[0], f1 = p[1], f2 = p[2], f3 = p[3];
        r[0].x = packbf(f0.x, f0.y); r[0].y = packbf(f0.z, f0.w);
        r[0].z = packbf(f1.x, f1.y); r[0].w = packbf(f1.z, f1.w);
        r[1].x = packbf(f2.x, f2.y); r[1].y = packbf(f2.z, f2.w);
        r[1].z = packbf(f3.x, f3.y); r[1].w = packbf(f3.z, f3.w);
    } else if (MODE == 2) {
        const __nv_bfloat16* g = (const __nv_bfloat16*)gp;
        int kw = tid >> 5, x4 = (tid & 31) << 2;
        const __nv_bfloat16* base = g + (size_t)(k0 + 2 * kw) * ld + x4;
        uint2 u0 = *(const uint2*)base;
        uint2 u1 = *(const uint2*)(base + ld);
        uint2 u2 = *(const uint2*)(base + (size_t)16 * ld);
        uint2 u3 = *(const uint2*)(base + (size_t)17 * ld);
        r[0].x = u0.x; r[0].y = u0.y; r[0].z = u1.x; r[0].w = u1.y;
        r[1].x = u2.x; r[1].y = u2.y; r[1].z = u3.x; r[1].w = u3.y;
    } else {
        const float* g = (const float*)gp;
        int kw = tid >> 5, x4 = (tid & 31) << 2;
        int kr = k0 + 2 * kw;
        const float* base = g + (size_t)kr * ld + x4;
        float4 f0 = *(const float4*)base;
        float4 f1 = *(const float4*)(base + ld);
        float4 f2 = *(const float4*)(base + (size_t)16 * ld);
        float4 f3 = *(const float4*)(base + (size_t)17 * ld);
        float s0 = sc[kr],      o0 = sb[kr];
        float s1 = sc[kr + 1],  o1 = sb[kr + 1];
        float s2 = sc[kr + 16], o2 = sb[kr + 16];
        float s3 = sc[kr + 17], o3 = sb[kr + 17];
        r[0].x = packbf(f0.x * s0 + o0, f0.y * s0 + o0);
        r[0].y = packbf(f0.z * s0 + o0, f0.w * s0 + o0);
        r[0].z = packbf(f1.x * s1 + o1, f1.y * s1 + o1);
        r[0].w = packbf(f1.z * s1 + o1, f1.w * s1 + o1);
        r[1].x = packbf(f2.x * s2 + o2, f2.y * s2 + o2);
        r[1].y = packbf(f2.z * s2 + o2, f2.w * s2 + o2);
        r[1].z = packbf(f3.x * s3 + o3, f3.y * s3 + o3);
        r[1].w = packbf(f3.z * s3 + o3, f3.w * s3 + o3);
    }
}

template <int MODE>
__device__ __forceinline__ void sts_bf(uint32_t* s, int tid, const uint4 r[2]) {
    if (MODE >= 2) {
        int kw = tid >> 5, xw = (tid & 31) * 2;
        *(uint2*)(s + (2 * kw) * KTS + xw)      = make_uint2(r[0].x, r[0].y);
        *(uint2*)(s + (2 * kw + 1) * KTS + xw)  = make_uint2(r[0].z, r[0].w);
        *(uint2*)(s + (2 * kw + 16) * KTS + xw) = make_uint2(r[1].x, r[1].y);
        *(uint2*)(s + (2 * kw + 17) * KTS + xw) = make_uint2(r[1].z, r[1].w);
    } else {
        int x = tid >> 1, kq8 = (tid & 1) << 3;
        *(uint4*)(s + x * BSKC + kq8)     = r[0];
        *(uint4*)(s + x * BSKC + kq8 + 4) = r[1];
    }
}

template <int AM, int BM>
__device__ __forceinline__ void gemm_bf(const void* Ag, int lda,
                                        const void* Bg, int ldb,
                                        int K, float acc[4][4][4],
                                        const float* bsc = nullptr,
                                        const float* bsb = nullptr) {
    __shared__ uint32_t sm[2][2][BSMW];
    const int tid = threadIdx.x;
    const int warp = tid >> 5, lane = tid & 31;
    const int mBase = (warp >> 2) * 64;
    const int nBase = (warp & 3) * 32;
    // ldmatrix lane decomposition
    const int l8 = lane & 7, lb3 = (lane >> 3) & 1, lb4 = (lane >> 4) & 1;
    const int lm = lane & 15, lm8 = lm & 7, lmb3 = (lm >> 3) & 1;

    const uint32_t smAddr = (uint32_t)__cvta_generic_to_shared(&sm[0][0][0]);

    uint4 ra[2], rb[2];
    ldg_bf<AM>(Ag, lda, 0, tid, ra, nullptr, nullptr);
    ldg_bf<BM>(Bg, ldb, 0, tid, rb, bsc, bsb);
    sts_bf<AM>(sm[0][0], tid, ra);
    sts_bf<BM>(sm[0][1], tid, rb);
    __syncthreads();

    const int nk = K >> 5;
    for (int ik = 0; ik < nk; ik++) {
        const int cur = ik & 1;
        if (ik + 1 < nk) {
            ldg_bf<AM>(Ag, lda, (ik + 1) << 5, tid, ra, nullptr, nullptr);
            ldg_bf<BM>(Bg, ldb, (ik + 1) << 5, tid, rb, bsc, bsb);
        }
        const uint32_t baseA = smAddr + (uint32_t)(cur * 2 + 0) * (BSMW * 4);
        const uint32_t baseB = smAddr + (uint32_t)(cur * 2 + 1) * (BSMW * 4);
#pragma unroll
        for (int kks = 0; kks < 2; kks++) {
            uint32_t a[4][4], b[4][2];
#pragma unroll
            for (int i = 0; i < 4; i++) {
                uint32_t ad;
                if (AM < 2)
                    ad = baseA + (uint32_t)(((mBase + i * 16 + l8 + lb3 * 8) * BSKC
                                             + kks * 8 + lb4 * 4) << 2);
                else
                    ad = baseA + (uint32_t)(((kks * 16 + l8 + lb4 * 8) * KTS) << 2)
                               + (uint32_t)((mBase + i * 16 + lb3 * 8) << 1);
                if (AM < 2) ldsm_x4(a[i], ad); else ldsm_x4t(a[i], ad);
            }
#pragma unroll
            for (int j = 0; j < 4; j++) {
                uint32_t bd;
                if (BM < 2)
                    bd = baseB + (uint32_t)(((nBase + j * 8 + lm8) * BSKC
                                             + kks * 8 + lmb3 * 4) << 2);
                else
                    bd = baseB + (uint32_t)(((kks * 16 + lm8 + lmb3 * 8) * KTS) << 2)
                               + (uint32_t)((nBase + j * 8) << 1);
                if (BM < 2) ldsm_x2(b[j], bd); else ldsm_x2t(b[j], bd);
            }
#pragma unroll
            for (int i = 0; i < 4; i++)
#pragma unroll
                for (int j = 0; j < 4; j++)
                    asm("mma.sync.aligned.m16n8k16.row.col.f32.bf16.bf16.f32 "
                        "{%0,%1,%2,%3},{%4,%5,%6,%7},{%8,%9},{%0,%1,%2,%3};"
                        : "+f"(acc[i][j][0]), "+f"(acc[i][j][1]),
                          "+f"(acc[i][j][2]), "+f"(acc[i][j][3])
                        : "r"(a[i][0]), "r"(a[i][1]), "r"(a[i][2]), "r"(a[i][3]),
                          "r"(b[j][0]), "r"(b[j][1]));
        }
        if (ik + 1 < nk) {
            sts_bf<AM>(sm[cur ^ 1][0], tid, ra);
            sts_bf<BM>(sm[cur ^ 1][1], tid, rb);
        }
        __syncthreads();
    }
}

// ---------------------------------------------------------------------------
// QKV = qkv_w(1536x512) @ gn(x)(512xT)  [bf16, GN fused into B load]
// ---------------------------------------------------------------------------
__global__ void __launch_bounds__(256, 2) k_qkv(const float* __restrict__ W,
                                                const float* __restrict__ bias,
                                                const float* __restrict__ x) {
    int n  = blockIdx.z;
    int m0 = blockIdx.y * 128;
    int t0 = blockIdx.x * 128;
    float acc[4][4][4] = {};
    gemm_bf<1, 3>(W + (size_t)m0 * C, C,
                  x + (size_t)n * C * T + t0, T, C, acc,
                  g_sc + n * C, g_sb + n * C);

    int which = m0 >> 9;
    __nv_bfloat16* dst =
        (which == 0 ? g_q : which == 1 ? g_k : g_v) + (size_t)n * C * T;
    int dbase = m0 & (C - 1);
    const int warp = threadIdx.x >> 5, lane = threadIdx.x & 31;
    const int g = lane >> 2, tg = lane & 3;
    const int mB = (warp >> 2) * 64, nB = (warp & 3) * 32;
#pragma unroll
    for (int i = 0; i < 4; i++) {
        int r = mB + i * 16 + g;
        float bv0 = bias[m0 + r];
        float bv1 = bias[m0 + r + 8];
#pragma unroll
        for (int j = 0; j < 4; j++) {
            int col = t0 + nB + j * 8 + tg * 2;
            uint32_t w0 = packbf(acc[i][j][0] + bv0, acc[i][j][1] + bv0);
            uint32_t w1 = packbf(acc[i][j][2] + bv1, acc[i][j][3] + bv1);
            *(uint32_t*)&dst[(size_t)(dbase + r) * T + col]     = w0;
            *(uint32_t*)&dst[(size_t)(dbase + r + 8) * T + col] = w1;
        }
    }
}

// ---------------------------------------------------------------------------
// p[t][s] = exp(scale * q.k)  [bf16 KT x KT] ; also per-(row, s-tile) sums
// (max-free: scores ~ N(0,1), |S| < ~8, exp is safe in fp32/bf16)
// ---------------------------------------------------------------------------
__global__ void __launch_bounds__(256, 2) k_scores() {
    int n  = blockIdx.z;
    int t0 = blockIdx.y * 128;
    int s0 = blockIdx.x * 128;
    float acc[4][4][4] = {};
    gemm_bf<2, 2>(g_q + (size_t)n * C * T + t0, T,
                  g_k + (size_t)n * C * T + s0, T, C, acc);

    const float scale = 0.04419417382415922f;  // 512^-0.5
    __nv_bfloat16* dst = g_p + (size_t)n * T * T;
    __shared__ float sm_l[128][4];
    const int warp = threadIdx.x >> 5, lane = threadIdx.x & 31;
    const int g = lane >> 2, tg = lane & 3;
    const int mB = (warp >> 2) * 64, nB = (warp & 3) * 32;
#pragma unroll
    for (int i = 0; i < 4; i++) {
        int r = t0 + mB + i * 16 + g;
        float ps0 = 0.f, ps1 = 0.f;
#pragma unroll
        for (int j = 0; j < 4; j++) {
            int col = s0 + nB + j * 8 + tg * 2;
            float e0 = __expf(acc[i][j][0] * scale);
            float e1 = __expf(acc[i][j][1] * scale);
            float e2 = __expf(acc[i][j][2] * scale);
            float e3 = __expf(acc[i][j][3] * scale);
            ps0 += e0 + e1;
            ps1 += e2 + e3;
            *(uint32_t*)&dst[(size_t)r * T + col]       = packbf(e0, e1);
            *(uint32_t*)&dst[(size_t)(r + 8) * T + col] = packbf(e2, e3);
        }
        // reduce across the 4 lanes of the quad (same rows, different cols)
        ps0 += __shfl_xor_sync(0xffffffffu, ps0, 1);
        ps0 += __shfl_xor_sync(0xffffffffu, ps0, 2);
        ps1 += __shfl_xor_sync(0xffffffffu, ps1, 1);
        ps1 += __shfl_xor_sync(0xffffffffu, ps1, 2);
        if (tg == 0) {
            sm_l[mB + i * 16 + g][warp & 3]     = ps0;
            sm_l[mB + i * 16 + g + 8][warp & 3] = ps1;
        }
    }
    __syncthreads();
    if (threadIdx.x < 128) {
        float l = sm_l[threadIdx.x][0] + sm_l[threadIdx.x][1]
                + sm_l[threadIdx.x][2] + sm_l[threadIdx.x][3];
        g_lp[((size_t)n * 32 + (s0 >> 7)) * T + t0 + threadIdx.x] = l;
    }
}

// ---------------------------------------------------------------------------
// inv row sum: l[n][t] = 1 / sum_i lp[n][i][t]   (fixed order, deterministic)
// ---------------------------------------------------------------------------
__global__ void __launch_bounds__(256) k_lsum() {
    int idx = blockIdx.x * 256 + threadIdx.x;      // idx over NB*T
    int n = idx >> 12, t = idx & (T - 1);
    const float* lp = g_lp + (size_t)n * 32 * T + t;
    float l = 0.f;
#pragma unroll
    for (int i = 0; i < 32; i++) l += lp[(size_t)i * T];
    g_li[idx] = 1.f / l;
}

// ---------------------------------------------------------------------------
// o[t][c] = inv_l[t] * sum_s p[t][s] * v[c][s]  [bf16 KC x KC] -> bf16 g_o
// ---------------------------------------------------------------------------
__global__ void __launch_bounds__(256, 2) k_av() {
    int n  = blockIdx.z;
    int t0 = blockIdx.y * 128;
    int c0 = blockIdx.x * 128;
    float acc[4][4][4] = {};
    gemm_bf<0, 0>(g_p + (size_t)n * T * T + (size_t)t0 * T, T,
                  g_v + (size_t)n * C * T + (size_t)c0 * T, T, T, acc);

    __nv_bfloat16* dst = g_o + (size_t)n * T * C;
    const int warp = threadIdx.x >> 5, lane = threadIdx.x & 31;
    const int g = lane >> 2, tg = lane & 3;
    const int mB = (warp >> 2) * 64, nB = (warp & 3) * 32;
#pragma unroll
    for (int i = 0; i < 4; i++) {
        int r = t0 + mB + i * 16 + g;
        float inv0 = g_li[n * T + r];
        float inv1 = g_li[n * T + r + 8];
#pragma unroll
        for (int j = 0; j < 4; j++) {
            int col = c0 + nB + j * 8 + tg * 2;
            uint32_t w0 = packbf(acc[i][j][0] * inv0, acc[i][j][1] * inv0);
            uint32_t w1 = packbf(acc[i][j][2] * inv1, acc[i][j][3] * inv1);
            *(uint32_t*)&dst[(size_t)r * C + col]       = w0;
            *(uint32_t*)&dst[(size_t)(r + 8) * C + col] = w1;
        }
    }
}

// ---------------------------------------------------------------------------
// out[n][d][t] = proj_w[d][:] . o[t][:] + proj_b[d] + x[n][d][t]  [bf16]
// ---------------------------------------------------------------------------
__global__ void __launch_bounds__(256, 2) k_proj(const float* __restrict__ W,
                                                 const float* __restrict__ bias,
                                                 const float* __restrict__ x,
                                                 float* __restrict__ out) {
    int n  = blockIdx.z;
    int d0 = blockIdx.y * 128;
    int t0 = blockIdx.x * 128;
    float acc[4][4][4] = {};
    gemm_bf<1, 0>(W + (size_t)d0 * C, C,
                  g_o + (size_t)n * T * C + (size_t)t0 * C, C, C, acc);

    const int warp = threadIdx.x >> 5, lane = threadIdx.x & 31;
    const int g = lane >> 2, tg = lane & 3;
    const int mB = (warp >> 2) * 64, nB = (warp & 3) * 32;
#pragma unroll
    for (int i = 0; i < 4; i++) {
        int d = d0 + mB + i * 16 + g;
        float bv0 = bias[d];
        float bv1 = bias[d + 8];
#pragma unroll
        for (int j = 0; j < 4; j++) {
            int col = t0 + nB + j * 8 + tg * 2;
            size_t base0 = ((size_t)n * C + d) * T + col;
            size_t base1 = ((size_t)n * C + d + 8) * T + col;
            float2 x0 = *(const float2*)&x[base0];
            float2 x1 = *(const float2*)&x[base1];
            float2 v0 = { acc[i][j][0] + bv0 + x0.x, acc[i][j][1] + bv0 + x0.y };
            float2 v1 = { acc[i][j][2] + bv1 + x1.x, acc[i][j][3] + bv1 + x1.y };
            *(float2*)&out[base0] = v0;
            *(float2*)&out[base1] = v1;
        }
    }
}

// ---------------------------------------------------------------------------
extern "C" void kernel_launch(void* const* d_in, const int* in_sizes, int n_in,
                              void* d_out, int out_size) {
    const float* x      = (const float*)d_in[0];
    const float* gn_w   = (const float*)d_in[1];
    const float* gn_b   = (const float*)d_in[2];
    const float* qkv_w  = (const float*)d_in[3];
    const float* qkv_b  = (const float*)d_in[4];
    const float* proj_w = (const float*)d_in[5];
    const float* proj_b = (const float*)d_in[6];
    float* out = (float*)d_out;

    gn_stats<<<NB * GROUPS, 256>>>(x, gn_w, gn_b);
    k_qkv   <<<dim3(T / 128, (3 * C) / 128, NB), 256>>>(qkv_w, qkv_b, x);
    k_scores<<<dim3(T / 128, T / 128, NB), 256>>>();
    k_lsum  <<<NB * T / 256, 256>>>();
    k_av    <<<dim3(C / 128, T / 128, NB), 256>>>();
    k_proj  <<<dim3(T / 128, C / 128, NB), 256>>>(proj_w, proj_b, x, out);
}

// round 12
// speedup vs baseline: 5.5511x; 1.0867x over previous
#include <cuda_runtime.h>
#include <cuda_bf16.h>
#include <cstdint>

#define NB 8
#define C 512
#define T 4096
#define GROUPS 32
#define CPG (C / GROUPS)      // 16
#define GSZ (CPG * T)         // 65536 elements per group

// Scratch (device globals; no allocations allowed)
__device__ float g_sc[NB * C];                         // GN scale  per (n,c)
__device__ float g_sb[NB * C];                         // GN shift  per (n,c)
__device__ __nv_bfloat16 g_q[(size_t)NB * C * T];      // [N][C][T]
__device__ __nv_bfloat16 g_k[(size_t)NB * C * T];      // [N][C][T]
__device__ __nv_bfloat16 g_v[(size_t)NB * C * T];      // [N][C][T]
__device__ __nv_bfloat16 g_o[(size_t)NB * T * C];      // [N][T][C]
__device__ __nv_bfloat16 g_p[(size_t)NB * T * T];      // [N][T][T] bf16 exp(S)
__device__ float g_lp[(size_t)NB * 32 * T];            // partial row sums
__device__ float g_li[NB * T];                         // 1 / row sum

// ---------------------------------------------------------------------------
// GroupNorm stats: one block per (n, group); writes per-channel scale/shift
// ---------------------------------------------------------------------------
__global__ void __launch_bounds__(256) gn_stats(const float* __restrict__ x,
                                                const float* __restrict__ w,
                                                const float* __restrict__ b) {
    int n = blockIdx.x >> 5;
    int g = blockIdx.x & 31;
    const float4* xp = (const float4*)(x + ((size_t)n * C + g * CPG) * T);
    const int NV = GSZ / 4;

    float s = 0.f, s2 = 0.f;
    for (int i = threadIdx.x; i < NV; i += 256) {
        float4 v = xp[i];
        s  += v.x + v.y + v.z + v.w;
        s2 += v.x * v.x + v.y * v.y + v.z * v.z + v.w * v.w;
    }
    __shared__ float rs[32], rs2[32];
    int lid = threadIdx.x & 31, wid = threadIdx.x >> 5;
#pragma unroll
    for (int o = 16; o; o >>= 1) {
        s  += __shfl_xor_sync(0xffffffffu, s, o);
        s2 += __shfl_xor_sync(0xffffffffu, s2, o);
    }
    if (lid == 0) { rs[wid] = s; rs2[wid] = s2; }
    __syncthreads();
    if (wid == 0) {
        s  = (lid < 8) ? rs[lid]  : 0.f;
        s2 = (lid < 8) ? rs2[lid] : 0.f;
#pragma unroll
        for (int o = 4; o; o >>= 1) {
            s  += __shfl_xor_sync(0xffffffffu, s, o);
            s2 += __shfl_xor_sync(0xffffffffu, s2, o);
        }
        if (lid == 0) { rs[0] = s; rs2[0] = s2; }
    }
    __syncthreads();
    float mean = rs[0] * (1.f / GSZ);
    float var  = rs2[0] * (1.f / GSZ) - mean * mean;
    float inv  = rsqrtf(var + 1e-5f);

    if (threadIdx.x < CPG) {
        int c = g * CPG + threadIdx.x;
        float scv = w[c] * inv;
        g_sc[n * C + c] = scv;
        g_sb[n * C + c] = b[c] - mean * scv;
    }
}

// ===========================================================================
// Common helpers
// ===========================================================================
#define BSKC 20
#define KTS  68
#define BSMW 2560

__device__ __forceinline__ uint32_t packbf(float lo, float hi) {
    __nv_bfloat162 h = __float22bfloat162_rn(make_float2(lo, hi));
    return *(uint32_t*)&h;
}

__device__ __forceinline__ void ldsm_x4(uint32_t a[4], uint32_t addr) {
    asm volatile("ldmatrix.sync.aligned.m8n8.x4.shared.b16 {%0,%1,%2,%3}, [%4];"
                 : "=r"(a[0]), "=r"(a[1]), "=r"(a[2]), "=r"(a[3]) : "r"(addr));
}
__device__ __forceinline__ void ldsm_x4t(uint32_t a[4], uint32_t addr) {
    asm volatile("ldmatrix.sync.aligned.m8n8.x4.trans.shared.b16 {%0,%1,%2,%3}, [%4];"
                 : "=r"(a[0]), "=r"(a[1]), "=r"(a[2]), "=r"(a[3]) : "r"(addr));
}
__device__ __forceinline__ void ldsm_x2(uint32_t b[2], uint32_t addr) {
    asm volatile("ldmatrix.sync.aligned.m8n8.x2.shared.b16 {%0,%1}, [%2];"
                 : "=r"(b[0]), "=r"(b[1]) : "r"(addr));
}
__device__ __forceinline__ void ldsm_x2t(uint32_t b[2], uint32_t addr) {
    asm volatile("ldmatrix.sync.aligned.m8n8.x2.trans.shared.b16 {%0,%1}, [%2];"
                 : "=r"(b[0]), "=r"(b[1]) : "r"(addr));
}
__device__ __forceinline__ void mma_bf16(float acc[4], const uint32_t a[4],
                                         const uint32_t b[2]) {
    asm("mma.sync.aligned.m16n8k16.row.col.f32.bf16.bf16.f32 "
        "{%0,%1,%2,%3},{%4,%5,%6,%7},{%8,%9},{%0,%1,%2,%3};"
        : "+f"(acc[0]), "+f"(acc[1]), "+f"(acc[2]), "+f"(acc[3])
        : "r"(a[0]), "r"(a[1]), "r"(a[2]), "r"(a[3]), "r"(b[0]), "r"(b[1]));
}

// ===========================================================================
// mma.sync bf16 GEMM core, register double-buffer (proven R8 machinery)
//   MODE 0: KC bf16; MODE 1: KC fp32; MODE 2: KT bf16; MODE 3: KT fp32 + GN
// ===========================================================================
template <int MODE>
__device__ __forceinline__ void ldg_bf(const void* gp, int ld, int k0, int tid,
                                       uint4 r[2],
                                       const float* __restrict__ sc,
                                       const float* __restrict__ sb) {
    if (MODE == 0) {
        const __nv_bfloat16* g = (const __nv_bfloat16*)gp;
        int x = tid >> 1, kq = (tid & 1) << 4;
        const uint4* p = (const uint4*)(g + (size_t)x * ld + k0 + kq);
        r[0] = p[0];
        r[1] = p[1];
    } else if (MODE == 1) {
        const float* g = (const float*)gp;
        int x = tid >> 1, kq = (tid & 1) << 4;
        const float4* p = (const float4*)(g + (size_t)x * ld + k0 + kq);
        float4 f0 = p[0], f1 = p[1], f2 = p[2], f3 = p[3];
        r[0].x = packbf(f0.x, f0.y); r[0].y = packbf(f0.z, f0.w);
        r[0].z = packbf(f1.x, f1.y); r[0].w = packbf(f1.z, f1.w);
        r[1].x = packbf(f2.x, f2.y); r[1].y = packbf(f2.z, f2.w);
        r[1].z = packbf(f3.x, f3.y); r[1].w = packbf(f3.z, f3.w);
    } else if (MODE == 2) {
        const __nv_bfloat16* g = (const __nv_bfloat16*)gp;
        int kw = tid >> 5, x4 = (tid & 31) << 2;
        const __nv_bfloat16* base = g + (size_t)(k0 + 2 * kw) * ld + x4;
        uint2 u0 = *(const uint2*)base;
        uint2 u1 = *(const uint2*)(base + ld);
        uint2 u2 = *(const uint2*)(base + (size_t)16 * ld);
        uint2 u3 = *(const uint2*)(base + (size_t)17 * ld);
        r[0].x = u0.x; r[0].y = u0.y; r[0].z = u1.x; r[0].w = u1.y;
        r[1].x = u2.x; r[1].y = u2.y; r[1].z = u3.x; r[1].w = u3.y;
    } else {
        const float* g = (const float*)gp;
        int kw = tid >> 5, x4 = (tid & 31) << 2;
        int kr = k0 + 2 * kw;
        const float* base = g + (size_t)kr * ld + x4;
        float4 f0 = *(const float4*)base;
        float4 f1 = *(const float4*)(base + ld);
        float4 f2 = *(const float4*)(base + (size_t)16 * ld);
        float4 f3 = *(const float4*)(base + (size_t)17 * ld);
        float s0 = sc[kr],      o0 = sb[kr];
        float s1 = sc[kr + 1],  o1 = sb[kr + 1];
        float s2 = sc[kr + 16], o2 = sb[kr + 16];
        float s3 = sc[kr + 17], o3 = sb[kr + 17];
        r[0].x = packbf(f0.x * s0 + o0, f0.y * s0 + o0);
        r[0].y = packbf(f0.z * s0 + o0, f0.w * s0 + o0);
        r[0].z = packbf(f1.x * s1 + o1, f1.y * s1 + o1);
        r[0].w = packbf(f1.z * s1 + o1, f1.w * s1 + o1);
        r[1].x = packbf(f2.x * s2 + o2, f2.y * s2 + o2);
        r[1].y = packbf(f2.z * s2 + o2, f2.w * s2 + o2);
        r[1].z = packbf(f3.x * s3 + o3, f3.y * s3 + o3);
        r[1].w = packbf(f3.z * s3 + o3, f3.w * s3 + o3);
    }
}

template <int MODE>
__device__ __forceinline__ void sts_bf(uint32_t* s, int tid, const uint4 r[2]) {
    if (MODE >= 2) {
        int kw = tid >> 5, xw = (tid & 31) * 2;
        *(uint2*)(s + (2 * kw) * KTS + xw)      = make_uint2(r[0].x, r[0].y);
        *(uint2*)(s + (2 * kw + 1) * KTS + xw)  = make_uint2(r[0].z, r[0].w);
        *(uint2*)(s + (2 * kw + 16) * KTS + xw) = make_uint2(r[1].x, r[1].y);
        *(uint2*)(s + (2 * kw + 17) * KTS + xw) = make_uint2(r[1].z, r[1].w);
    } else {
        int x = tid >> 1, kq8 = (tid & 1) << 3;
        *(uint4*)(s + x * BSKC + kq8)     = r[0];
        *(uint4*)(s + x * BSKC + kq8 + 4) = r[1];
    }
}

template <int AM, int BM>
__device__ __forceinline__ void gemm_bf(const void* Ag, int lda,
                                        const void* Bg, int ldb,
                                        int K, float acc[4][4][4],
                                        const float* bsc = nullptr,
                                        const float* bsb = nullptr) {
    __shared__ uint32_t sm[2][2][BSMW];
    const int tid = threadIdx.x;
    const int warp = tid >> 5, lane = tid & 31;
    const int mBase = (warp >> 2) * 64;
    const int nBase = (warp & 3) * 32;
    const int l8 = lane & 7, lb3 = (lane >> 3) & 1, lb4 = (lane >> 4) & 1;
    const int lm = lane & 15, lm8 = lm & 7, lmb3 = (lm >> 3) & 1;

    const uint32_t smAddr = (uint32_t)__cvta_generic_to_shared(&sm[0][0][0]);

    uint4 ra[2], rb[2];
    ldg_bf<AM>(Ag, lda, 0, tid, ra, nullptr, nullptr);
    ldg_bf<BM>(Bg, ldb, 0, tid, rb, bsc, bsb);
    sts_bf<AM>(sm[0][0], tid, ra);
    sts_bf<BM>(sm[0][1], tid, rb);
    __syncthreads();

    const int nk = K >> 5;
    for (int ik = 0; ik < nk; ik++) {
        const int cur = ik & 1;
        if (ik + 1 < nk) {
            ldg_bf<AM>(Ag, lda, (ik + 1) << 5, tid, ra, nullptr, nullptr);
            ldg_bf<BM>(Bg, ldb, (ik + 1) << 5, tid, rb, bsc, bsb);
        }
        const uint32_t baseA = smAddr + (uint32_t)(cur * 2 + 0) * (BSMW * 4);
        const uint32_t baseB = smAddr + (uint32_t)(cur * 2 + 1) * (BSMW * 4);
#pragma unroll
        for (int kks = 0; kks < 2; kks++) {
            uint32_t a[4][4], b[4][2];
#pragma unroll
            for (int i = 0; i < 4; i++) {
                uint32_t ad;
                if (AM < 2)
                    ad = baseA + (uint32_t)(((mBase + i * 16 + l8 + lb3 * 8) * BSKC
                                             + kks * 8 + lb4 * 4) << 2);
                else
                    ad = baseA + (uint32_t)(((kks * 16 + l8 + lb4 * 8) * KTS) << 2)
                               + (uint32_t)((mBase + i * 16 + lb3 * 8) << 1);
                if (AM < 2) ldsm_x4(a[i], ad); else ldsm_x4t(a[i], ad);
            }
#pragma unroll
            for (int j = 0; j < 4; j++) {
                uint32_t bd;
                if (BM < 2)
                    bd = baseB + (uint32_t)(((nBase + j * 8 + lm8) * BSKC
                                             + kks * 8 + lmb3 * 4) << 2);
                else
                    bd = baseB + (uint32_t)(((kks * 16 + lm8 + lmb3 * 8) * KTS) << 2)
                               + (uint32_t)((nBase + j * 8) << 1);
                if (BM < 2) ldsm_x2(b[j], bd); else ldsm_x2t(b[j], bd);
            }
#pragma unroll
            for (int i = 0; i < 4; i++)
#pragma unroll
                for (int j = 0; j < 4; j++)
                    mma_bf16(acc[i][j], a[i], b[j]);
        }
        if (ik + 1 < nk) {
            sts_bf<AM>(sm[cur ^ 1][0], tid, ra);
            sts_bf<BM>(sm[cur ^ 1][1], tid, rb);
        }
        __syncthreads();
    }
}

// ===========================================================================
// cp.async 4-stage pipelined GEMM core (k_av only: both operands bf16 KC)
// Tile 128x128, KTILE=32. Per-stage: A 128x80B + B 128x80B = 20480 B.
// ===========================================================================
#define CATILE 20480
#define CA_SMEM (4 * CATILE)

__device__ __forceinline__ void ca_load(uint32_t sdst, const __nv_bfloat16* g,
                                        int ld, int tid) {
    int x = tid >> 2;          // 0..63
    int q = tid & 3;
    const char* gp = (const char*)g;
#pragma unroll
    for (int h = 0; h < 2; h++) {
        int row = x + h * 64;
        asm volatile("cp.async.cg.shared.global [%0], [%1], 16;"
                     :: "r"(sdst + row * 80 + q * 16),
                        "l"(gp + (size_t)row * ld * 2 + q * 16));
    }
}

__device__ __forceinline__ void gemm_ca(const __nv_bfloat16* __restrict__ Ag, int lda,
                                        const __nv_bfloat16* __restrict__ Bg, int ldb,
                                        int K, float acc[4][4][4], uint32_t sbase) {
    const int tid = threadIdx.x;
    const int warp = tid >> 5, lane = tid & 31;
    const int mBase = (warp >> 2) * 64;
    const int nBase = (warp & 3) * 32;
    const int l8 = lane & 7, lb3 = (lane >> 3) & 1, lb4 = (lane >> 4) & 1;
    const int lm = lane & 15, lm8 = lm & 7, lmb3 = (lm >> 3) & 1;

    const int nk = K >> 5;
#pragma unroll
    for (int s = 0; s < 3; s++) {
        if (s < nk) {
            ca_load(sbase + s * CATILE,         Ag + s * 32, lda, tid);
            ca_load(sbase + s * CATILE + 10240, Bg + s * 32, ldb, tid);
        }
        asm volatile("cp.async.commit_group;");
    }
    for (int ik = 0; ik < nk; ik++) {
        asm volatile("cp.async.wait_group 2;");
        __syncthreads();
        const uint32_t baseA = sbase + (ik & 3) * CATILE;
        const uint32_t baseB = baseA + 10240;
#pragma unroll
        for (int kks = 0; kks < 2; kks++) {
            uint32_t a[4][4], b[4][2];
#pragma unroll
            for (int i = 0; i < 4; i++)
                ldsm_x4(a[i], baseA + (uint32_t)(((mBase + i * 16 + l8 + lb3 * 8) * BSKC
                                                  + kks * 8 + lb4 * 4) << 2));
#pragma unroll
            for (int j = 0; j < 4; j++)
                ldsm_x2(b[j], baseB + (uint32_t)(((nBase + j * 8 + lm8) * BSKC
                                                  + kks * 8 + lmb3 * 4) << 2));
#pragma unroll
            for (int i = 0; i < 4; i++)
#pragma unroll
                for (int j = 0; j < 4; j++)
                    mma_bf16(acc[i][j], a[i], b[j]);
        }
        __syncthreads();
        if (ik + 3 < nk) {
            ca_load(sbase + ((ik + 3) & 3) * CATILE,         Ag + (ik + 3) * 32, lda, tid);
            ca_load(sbase + ((ik + 3) & 3) * CATILE + 10240, Bg + (ik + 3) * 32, ldb, tid);
        }
        asm volatile("cp.async.commit_group;");
    }
}

// ---------------------------------------------------------------------------
// QKV: q,k,v written [C][T] channel-major (exact R8)
// ---------------------------------------------------------------------------
__global__ void __launch_bounds__(256, 2) k_qkv(const float* __restrict__ W,
                                                const float* __restrict__ bias,
                                                const float* __restrict__ x) {
    int n  = blockIdx.z;
    int m0 = blockIdx.y * 128;
    int t0 = blockIdx.x * 128;
    float acc[4][4][4] = {};
    gemm_bf<1, 3>(W + (size_t)m0 * C, C,
                  x + (size_t)n * C * T + t0, T, C, acc,
                  g_sc + n * C, g_sb + n * C);

    int which = m0 >> 9;
    __nv_bfloat16* dst =
        (which == 0 ? g_q : which == 1 ? g_k : g_v) + (size_t)n * C * T;
    int dbase = m0 & (C - 1);
    const int warp = threadIdx.x >> 5, lane = threadIdx.x & 31;
    const int g = lane >> 2, tg = lane & 3;
    const int mB = (warp >> 2) * 64, nB = (warp & 3) * 32;
#pragma unroll
    for (int i = 0; i < 4; i++) {
        int r = mB + i * 16 + g;
        float bv0 = bias[m0 + r];
        float bv1 = bias[m0 + r + 8];
#pragma unroll
        for (int j = 0; j < 4; j++) {
            int col = t0 + nB + j * 8 + tg * 2;
            uint32_t w0 = packbf(acc[i][j][0] + bv0, acc[i][j][1] + bv0);
            uint32_t w1 = packbf(acc[i][j][2] + bv1, acc[i][j][3] + bv1);
            *(uint32_t*)&dst[(size_t)(dbase + r) * T + col]     = w0;
            *(uint32_t*)&dst[(size_t)(dbase + r + 8) * T + col] = w1;
        }
    }
}

// ---------------------------------------------------------------------------
// scores: p[t][s] = exp(scale * q.k); per-(row, s-tile) sums -> g_lp (R8)
// ---------------------------------------------------------------------------
__global__ void __launch_bounds__(256, 2) k_scores() {
    int n  = blockIdx.z;
    int t0 = blockIdx.y * 128;
    int s0 = blockIdx.x * 128;
    float acc[4][4][4] = {};
    gemm_bf<2, 2>(g_q + (size_t)n * C * T + t0, T,
                  g_k + (size_t)n * C * T + s0, T, C, acc);

    const float scale = 0.04419417382415922f;  // 512^-0.5
    __nv_bfloat16* dst = g_p + (size_t)n * T * T;
    __shared__ float sm_l[128][4];
    const int warp = threadIdx.x >> 5, lane = threadIdx.x & 31;
    const int g = lane >> 2, tg = lane & 3;
    const int mB = (warp >> 2) * 64, nB = (warp & 3) * 32;
#pragma unroll
    for (int i = 0; i < 4; i++) {
        int r = t0 + mB + i * 16 + g;
        float ps0 = 0.f, ps1 = 0.f;
#pragma unroll
        for (int j = 0; j < 4; j++) {
            int col = s0 + nB + j * 8 + tg * 2;
            float e0 = __expf(acc[i][j][0] * scale);
            float e1 = __expf(acc[i][j][1] * scale);
            float e2 = __expf(acc[i][j][2] * scale);
            float e3 = __expf(acc[i][j][3] * scale);
            ps0 += e0 + e1;
            ps1 += e2 + e3;
            *(uint32_t*)&dst[(size_t)r * T + col]       = packbf(e0, e1);
            *(uint32_t*)&dst[(size_t)(r + 8) * T + col] = packbf(e2, e3);
        }
        ps0 += __shfl_xor_sync(0xffffffffu, ps0, 1);
        ps0 += __shfl_xor_sync(0xffffffffu, ps0, 2);
        ps1 += __shfl_xor_sync(0xffffffffu, ps1, 1);
        ps1 += __shfl_xor_sync(0xffffffffu, ps1, 2);
        if (tg == 0) {
            sm_l[mB + i * 16 + g][warp & 3]     = ps0;
            sm_l[mB + i * 16 + g + 8][warp & 3] = ps1;
        }
    }
    __syncthreads();
    if (threadIdx.x < 128) {
        float l = sm_l[threadIdx.x][0] + sm_l[threadIdx.x][1]
                + sm_l[threadIdx.x][2] + sm_l[threadIdx.x][3];
        g_lp[((size_t)n * 32 + blockIdx.x) * T + t0 + threadIdx.x] = l;
    }
}

// ---------------------------------------------------------------------------
// inv row sum (fixed order, deterministic)
// ---------------------------------------------------------------------------
__global__ void __launch_bounds__(256) k_lsum() {
    int idx = blockIdx.x * 256 + threadIdx.x;
    int n = idx >> 12, t = idx & (T - 1);
    const float* lp = g_lp + (size_t)n * 32 * T + t;
    float l = 0.f;
#pragma unroll
    for (int i = 0; i < 32; i++) l += lp[(size_t)i * T];
    g_li[idx] = 1.f / l;
}

// ---------------------------------------------------------------------------
// AV: o[t][c] = inv_l[t] * sum_s p[t][s] * v[c][s]  (cp.async pipeline core)
// ---------------------------------------------------------------------------
__global__ void __launch_bounds__(256, 2) k_av() {
    extern __shared__ char smraw[];
    uint32_t sbase = (uint32_t)__cvta_generic_to_shared(smraw);
    int n  = blockIdx.z;
    int t0 = blockIdx.y * 128;
    int c0 = blockIdx.x * 128;
    float acc[4][4][4] = {};
    gemm_ca(g_p + ((size_t)n * T + t0) * T, T,
            g_v + ((size_t)n * C + c0) * T, T, T, acc, sbase);

    __nv_bfloat16* dst = g_o + (size_t)n * T * C;
    const int warp = threadIdx.x >> 5, lane = threadIdx.x & 31;
    const int g = lane >> 2, tg = lane & 3;
    const int mB = (warp >> 2) * 64, nB = (warp & 3) * 32;
#pragma unroll
    for (int i = 0; i < 4; i++) {
        int r = t0 + mB + i * 16 + g;
        float inv0 = g_li[n * T + r];
        float inv1 = g_li[n * T + r + 8];
#pragma unroll
        for (int j = 0; j < 4; j++) {
            int col = c0 + nB + j * 8 + tg * 2;
            uint32_t w0 = packbf(acc[i][j][0] * inv0, acc[i][j][1] * inv0);
            uint32_t w1 = packbf(acc[i][j][2] * inv1, acc[i][j][3] * inv1);
            *(uint32_t*)&dst[(size_t)r * C + col]       = w0;
            *(uint32_t*)&dst[(size_t)(r + 8) * C + col] = w1;
        }
    }
}

// ---------------------------------------------------------------------------
// proj: out[n][d][t] = proj_w[d][:] . o[t][:] + proj_b[d] + x[n][d][t]
// ---------------------------------------------------------------------------
__global__ void __launch_bounds__(256, 2) k_proj(const float* __restrict__ W,
                                                 const float* __restrict__ bias,
                                                 const float* __restrict__ x,
                                                 float* __restrict__ out) {
    int n  = blockIdx.z;
    int d0 = blockIdx.y * 128;
    int t0 = blockIdx.x * 128;
    float acc[4][4][4] = {};
    gemm_bf<1, 0>(W + (size_t)d0 * C, C,
                  g_o + (size_t)n * T * C + (size_t)t0 * C, C, C, acc);

    const int warp = threadIdx.x >> 5, lane = threadIdx.x & 31;
    const int g = lane >> 2, tg = lane & 3;
    const int mB = (warp >> 2) * 64, nB = (warp & 3) * 32;
#pragma unroll
    for (int i = 0; i < 4; i++) {
        int d = d0 + mB + i * 16 + g;
        float bv0 = bias[d];
        float bv1 = bias[d + 8];
#pragma unroll
        for (int j = 0; j < 4; j++) {
            int col = t0 + nB + j * 8 + tg * 2;
            size_t base0 = ((size_t)n * C + d) * T + col;
            size_t base1 = ((size_t)n * C + d + 8) * T + col;
            float2 x0 = *(const float2*)&x[base0];
            float2 x1 = *(const float2*)&x[base1];
            float2 v0 = { acc[i][j][0] + bv0 + x0.x, acc[i][j][1] + bv0 + x0.y };
            float2 v1 = { acc[i][j][2] + bv1 + x1.x, acc[i][j][3] + bv1 + x1.y };
            *(float2*)&out[base0] = v0;
            *(float2*)&out[base1] = v1;
        }
    }
}

// ---------------------------------------------------------------------------
extern "C" void kernel_launch(void* const* d_in, const int* in_sizes, int n_in,
                              void* d_out, int out_size) {
    const float* x      = (const float*)d_in[0];
    const float* gn_w   = (const float*)d_in[1];
    const float* gn_b   = (const float*)d_in[2];
    const float* qkv_w  = (const float*)d_in[3];
    const float* qkv_b  = (const float*)d_in[4];
    const float* proj_w = (const float*)d_in[5];
    const float* proj_b = (const float*)d_in[6];
    float* out = (float*)d_out;

    cudaFuncSetAttribute(k_av, cudaFuncAttributeMaxDynamicSharedMemorySize, CA_SMEM);

    gn_stats<<<NB * GROUPS, 256>>>(x, gn_w, gn_b);
    k_qkv   <<<dim3(T / 128, (3 * C) / 128, NB), 256>>>(qkv_w, qkv_b, x);
    k_scores<<<dim3(T / 128, T / 128, NB), 256>>>();
    k_lsum  <<<NB * T / 256, 256>>>();
    k_av    <<<dim3(C / 128, T / 128, NB), 256, CA_SMEM>>>();
    k_proj  <<<dim3(T / 128, C / 128, NB), 256>>>(proj_w, proj_b, x, out);
}

// round 13
// speedup vs baseline: 5.6192x; 1.0123x over previous
#include <cuda_runtime.h>
#include <cuda_bf16.h>
#include <cstdint>

#define NB 8
#define C 512
#define T 4096
#define GROUPS 32
#define CPG (C / GROUPS)      // 16
#define GSZ (CPG * T)         // 65536 elements per group

// Scratch (device globals; no allocations allowed)
__device__ float g_sc[NB * C];                         // GN scale  per (n,c)
__device__ float g_sb[NB * C];                         // GN shift  per (n,c)
__device__ __nv_bfloat16 g_q[(size_t)NB * C * T];      // [N][C][T]
__device__ __nv_bfloat16 g_k[(size_t)NB * C * T];      // [N][C][T]
__device__ __nv_bfloat16 g_v[(size_t)NB * C * T];      // [N][C][T]
__device__ __nv_bfloat16 g_o[(size_t)NB * T * C];      // [N][T][C]
__device__ __nv_bfloat16 g_p[(size_t)NB * T * T];      // [N][T][T] bf16 exp(S)
__device__ float g_lp[(size_t)NB * 32 * T];            // partial row sums
__device__ float g_li[NB * T];                         // 1 / row sum

// ---------------------------------------------------------------------------
// GroupNorm stats: one block per (n, group); writes per-channel scale/shift
// ---------------------------------------------------------------------------
__global__ void __launch_bounds__(256) gn_stats(const float* __restrict__ x,
                                                const float* __restrict__ w,
                                                const float* __restrict__ b) {
    int n = blockIdx.x >> 5;
    int g = blockIdx.x & 31;
    const float4* xp = (const float4*)(x + ((size_t)n * C + g * CPG) * T);
    const int NV = GSZ / 4;

    float s = 0.f, s2 = 0.f;
    for (int i = threadIdx.x; i < NV; i += 256) {
        float4 v = xp[i];
        s  += v.x + v.y + v.z + v.w;
        s2 += v.x * v.x + v.y * v.y + v.z * v.z + v.w * v.w;
    }
    __shared__ float rs[32], rs2[32];
    int lid = threadIdx.x & 31, wid = threadIdx.x >> 5;
#pragma unroll
    for (int o = 16; o; o >>= 1) {
        s  += __shfl_xor_sync(0xffffffffu, s, o);
        s2 += __shfl_xor_sync(0xffffffffu, s2, o);
    }
    if (lid == 0) { rs[wid] = s; rs2[wid] = s2; }
    __syncthreads();
    if (wid == 0) {
        s  = (lid < 8) ? rs[lid]  : 0.f;
        s2 = (lid < 8) ? rs2[lid] : 0.f;
#pragma unroll
        for (int o = 4; o; o >>= 1) {
            s  += __shfl_xor_sync(0xffffffffu, s, o);
            s2 += __shfl_xor_sync(0xffffffffu, s2, o);
        }
        if (lid == 0) { rs[0] = s; rs2[0] = s2; }
    }
    __syncthreads();
    float mean = rs[0] * (1.f / GSZ);
    float var  = rs2[0] * (1.f / GSZ) - mean * mean;
    float inv  = rsqrtf(var + 1e-5f);

    if (threadIdx.x < CPG) {
        int c = g * CPG + threadIdx.x;
        float scv = w[c] * inv;
        g_sc[n * C + c] = scv;
        g_sb[n * C + c] = b[c] - mean * scv;
    }
}

// ===========================================================================
// Common helpers
// ===========================================================================
#define BSKC 20
#define KTS  68
#define BSMW 2560

__device__ __forceinline__ uint32_t packbf(float lo, float hi) {
    __nv_bfloat162 h = __float22bfloat162_rn(make_float2(lo, hi));
    return *(uint32_t*)&h;
}

__device__ __forceinline__ void ldsm_x4(uint32_t a[4], uint32_t addr) {
    asm volatile("ldmatrix.sync.aligned.m8n8.x4.shared.b16 {%0,%1,%2,%3}, [%4];"
                 : "=r"(a[0]), "=r"(a[1]), "=r"(a[2]), "=r"(a[3]) : "r"(addr));
}
__device__ __forceinline__ void ldsm_x4t(uint32_t a[4], uint32_t addr) {
    asm volatile("ldmatrix.sync.aligned.m8n8.x4.trans.shared.b16 {%0,%1,%2,%3}, [%4];"
                 : "=r"(a[0]), "=r"(a[1]), "=r"(a[2]), "=r"(a[3]) : "r"(addr));
}
__device__ __forceinline__ void ldsm_x2(uint32_t b[2], uint32_t addr) {
    asm volatile("ldmatrix.sync.aligned.m8n8.x2.shared.b16 {%0,%1}, [%2];"
                 : "=r"(b[0]), "=r"(b[1]) : "r"(addr));
}
__device__ __forceinline__ void ldsm_x2t(uint32_t b[2], uint32_t addr) {
    asm volatile("ldmatrix.sync.aligned.m8n8.x2.trans.shared.b16 {%0,%1}, [%2];"
                 : "=r"(b[0]), "=r"(b[1]) : "r"(addr));
}
__device__ __forceinline__ void mma_bf16(float acc[4], const uint32_t a[4],
                                         const uint32_t b[2]) {
    asm("mma.sync.aligned.m16n8k16.row.col.f32.bf16.bf16.f32 "
        "{%0,%1,%2,%3},{%4,%5,%6,%7},{%8,%9},{%0,%1,%2,%3};"
        : "+f"(acc[0]), "+f"(acc[1]), "+f"(acc[2]), "+f"(acc[3])
        : "r"(a[0]), "r"(a[1]), "r"(a[2]), "r"(a[3]), "r"(b[0]), "r"(b[1]));
}

// ===========================================================================
// mma.sync bf16 GEMM core, register double-buffer (qkv & proj)
//   MODE 0: KC bf16; MODE 1: KC fp32; MODE 2: KT bf16; MODE 3: KT fp32 + GN
// ===========================================================================
template <int MODE>
__device__ __forceinline__ void ldg_bf(const void* gp, int ld, int k0, int tid,
                                       uint4 r[2],
                                       const float* __restrict__ sc,
                                       const float* __restrict__ sb) {
    if (MODE == 0) {
        const __nv_bfloat16* g = (const __nv_bfloat16*)gp;
        int x = tid >> 1, kq = (tid & 1) << 4;
        const uint4* p = (const uint4*)(g + (size_t)x * ld + k0 + kq);
        r[0] = p[0];
        r[1] = p[1];
    } else if (MODE == 1) {
        const float* g = (const float*)gp;
        int x = tid >> 1, kq = (tid & 1) << 4;
        const float4* p = (const float4*)(g + (size_t)x * ld + k0 + kq);
        float4 f0 = p[0], f1 = p[1], f2 = p[2], f3 = p[3];
        r[0].x = packbf(f0.x, f0.y); r[0].y = packbf(f0.z, f0.w);
        r[0].z = packbf(f1.x, f1.y); r[0].w = packbf(f1.z, f1.w);
        r[1].x = packbf(f2.x, f2.y); r[1].y = packbf(f2.z, f2.w);
        r[1].z = packbf(f3.x, f3.y); r[1].w = packbf(f3.z, f3.w);
    } else if (MODE == 2) {
        const __nv_bfloat16* g = (const __nv_bfloat16*)gp;
        int kw = tid >> 5, x4 = (tid & 31) << 2;
        const __nv_bfloat16* base = g + (size_t)(k0 + 2 * kw) * ld + x4;
        uint2 u0 = *(const uint2*)base;
        uint2 u1 = *(const uint2*)(base + ld);
        uint2 u2 = *(const uint2*)(base + (size_t)16 * ld);
        uint2 u3 = *(const uint2*)(base + (size_t)17 * ld);
        r[0].x = u0.x; r[0].y = u0.y; r[0].z = u1.x; r[0].w = u1.y;
        r[1].x = u2.x; r[1].y = u2.y; r[1].z = u3.x; r[1].w = u3.y;
    } else {
        const float* g = (const float*)gp;
        int kw = tid >> 5, x4 = (tid & 31) << 2;
        int kr = k0 + 2 * kw;
        const float* base = g + (size_t)kr * ld + x4;
        float4 f0 = *(const float4*)base;
        float4 f1 = *(const float4*)(base + ld);
        float4 f2 = *(const float4*)(base + (size_t)16 * ld);
        float4 f3 = *(const float4*)(base + (size_t)17 * ld);
        float s0 = sc[kr],      o0 = sb[kr];
        float s1 = sc[kr + 1],  o1 = sb[kr + 1];
        float s2 = sc[kr + 16], o2 = sb[kr + 16];
        float s3 = sc[kr + 17], o3 = sb[kr + 17];
        r[0].x = packbf(f0.x * s0 + o0, f0.y * s0 + o0);
        r[0].y = packbf(f0.z * s0 + o0, f0.w * s0 + o0);
        r[0].z = packbf(f1.x * s1 + o1, f1.y * s1 + o1);
        r[0].w = packbf(f1.z * s1 + o1, f1.w * s1 + o1);
        r[1].x = packbf(f2.x * s2 + o2, f2.y * s2 + o2);
        r[1].y = packbf(f2.z * s2 + o2, f2.w * s2 + o2);
        r[1].z = packbf(f3.x * s3 + o3, f3.y * s3 + o3);
        r[1].w = packbf(f3.z * s3 + o3, f3.w * s3 + o3);
    }
}

template <int MODE>
__device__ __forceinline__ void sts_bf(uint32_t* s, int tid, const uint4 r[2]) {
    if (MODE >= 2) {
        int kw = tid >> 5, xw = (tid & 31) * 2;
        *(uint2*)(s + (2 * kw) * KTS + xw)      = make_uint2(r[0].x, r[0].y);
        *(uint2*)(s + (2 * kw + 1) * KTS + xw)  = make_uint2(r[0].z, r[0].w);
        *(uint2*)(s + (2 * kw + 16) * KTS + xw) = make_uint2(r[1].x, r[1].y);
        *(uint2*)(s + (2 * kw + 17) * KTS + xw) = make_uint2(r[1].z, r[1].w);
    } else {
        int x = tid >> 1, kq8 = (tid & 1) << 3;
        *(uint4*)(s + x * BSKC + kq8)     = r[0];
        *(uint4*)(s + x * BSKC + kq8 + 4) = r[1];
    }
}

template <int AM, int BM>
__device__ __forceinline__ void gemm_bf(const void* Ag, int lda,
                                        const void* Bg, int ldb,
                                        int K, float acc[4][4][4],
                                        const float* bsc = nullptr,
                                        const float* bsb = nullptr) {
    __shared__ uint32_t sm[2][2][BSMW];
    const int tid = threadIdx.x;
    const int warp = tid >> 5, lane = tid & 31;
    const int mBase = (warp >> 2) * 64;
    const int nBase = (warp & 3) * 32;
    const int l8 = lane & 7, lb3 = (lane >> 3) & 1, lb4 = (lane >> 4) & 1;
    const int lm = lane & 15, lm8 = lm & 7, lmb3 = (lm >> 3) & 1;

    const uint32_t smAddr = (uint32_t)__cvta_generic_to_shared(&sm[0][0][0]);

    uint4 ra[2], rb[2];
    ldg_bf<AM>(Ag, lda, 0, tid, ra, nullptr, nullptr);
    ldg_bf<BM>(Bg, ldb, 0, tid, rb, bsc, bsb);
    sts_bf<AM>(sm[0][0], tid, ra);
    sts_bf<BM>(sm[0][1], tid, rb);
    __syncthreads();

    const int nk = K >> 5;
    for (int ik = 0; ik < nk; ik++) {
        const int cur = ik & 1;
        if (ik + 1 < nk) {
            ldg_bf<AM>(Ag, lda, (ik + 1) << 5, tid, ra, nullptr, nullptr);
            ldg_bf<BM>(Bg, ldb, (ik + 1) << 5, tid, rb, bsc, bsb);
        }
        const uint32_t baseA = smAddr + (uint32_t)(cur * 2 + 0) * (BSMW * 4);
        const uint32_t baseB = smAddr + (uint32_t)(cur * 2 + 1) * (BSMW * 4);
#pragma unroll
        for (int kks = 0; kks < 2; kks++) {
            uint32_t a[4][4], b[4][2];
#pragma unroll
            for (int i = 0; i < 4; i++) {
                uint32_t ad;
                if (AM < 2)
                    ad = baseA + (uint32_t)(((mBase + i * 16 + l8 + lb3 * 8) * BSKC
                                             + kks * 8 + lb4 * 4) << 2);
                else
                    ad = baseA + (uint32_t)(((kks * 16 + l8 + lb4 * 8) * KTS) << 2)
                               + (uint32_t)((mBase + i * 16 + lb3 * 8) << 1);
                if (AM < 2) ldsm_x4(a[i], ad); else ldsm_x4t(a[i], ad);
            }
#pragma unroll
            for (int j = 0; j < 4; j++) {
                uint32_t bd;
                if (BM < 2)
                    bd = baseB + (uint32_t)(((nBase + j * 8 + lm8) * BSKC
                                             + kks * 8 + lmb3 * 4) << 2);
                else
                    bd = baseB + (uint32_t)(((kks * 16 + lm8 + lmb3 * 8) * KTS) << 2)
                               + (uint32_t)((nBase + j * 8) << 1);
                if (BM < 2) ldsm_x2(b[j], bd); else ldsm_x2t(b[j], bd);
            }
#pragma unroll
            for (int i = 0; i < 4; i++)
#pragma unroll
                for (int j = 0; j < 4; j++)
                    mma_bf16(acc[i][j], a[i], b[j]);
        }
        if (ik + 1 < nk) {
            sts_bf<AM>(sm[cur ^ 1][0], tid, ra);
            sts_bf<BM>(sm[cur ^ 1][1], tid, rb);
        }
        __syncthreads();
    }
}

// ===========================================================================
// cp.async 4-stage pipelined GEMM core, KC variant (k_av)
// ===========================================================================
#define CATILE 20480
#define CA_SMEM (4 * CATILE)

__device__ __forceinline__ void ca_load(uint32_t sdst, const __nv_bfloat16* g,
                                        int ld, int tid) {
    int x = tid >> 2;          // 0..63
    int q = tid & 3;
    const char* gp = (const char*)g;
#pragma unroll
    for (int h = 0; h < 2; h++) {
        int row = x + h * 64;
        asm volatile("cp.async.cg.shared.global [%0], [%1], 16;"
                     :: "r"(sdst + row * 80 + q * 16),
                        "l"(gp + (size_t)row * ld * 2 + q * 16));
    }
}

__device__ __forceinline__ void gemm_ca(const __nv_bfloat16* __restrict__ Ag, int lda,
                                        const __nv_bfloat16* __restrict__ Bg, int ldb,
                                        int K, float acc[4][4][4], uint32_t sbase) {
    const int tid = threadIdx.x;
    const int warp = tid >> 5, lane = tid & 31;
    const int mBase = (warp >> 2) * 64;
    const int nBase = (warp & 3) * 32;
    const int l8 = lane & 7, lb3 = (lane >> 3) & 1, lb4 = (lane >> 4) & 1;
    const int lm = lane & 15, lm8 = lm & 7, lmb3 = (lm >> 3) & 1;

    const int nk = K >> 5;
#pragma unroll
    for (int s = 0; s < 3; s++) {
        if (s < nk) {
            ca_load(sbase + s * CATILE,         Ag + s * 32, lda, tid);
            ca_load(sbase + s * CATILE + 10240, Bg + s * 32, ldb, tid);
        }
        asm volatile("cp.async.commit_group;");
    }
    for (int ik = 0; ik < nk; ik++) {
        asm volatile("cp.async.wait_group 2;");
        __syncthreads();
        const uint32_t baseA = sbase + (ik & 3) * CATILE;
        const uint32_t baseB = baseA + 10240;
#pragma unroll
        for (int kks = 0; kks < 2; kks++) {
            uint32_t a[4][4], b[4][2];
#pragma unroll
            for (int i = 0; i < 4; i++)
                ldsm_x4(a[i], baseA + (uint32_t)(((mBase + i * 16 + l8 + lb3 * 8) * BSKC
                                                  + kks * 8 + lb4 * 4) << 2));
#pragma unroll
            for (int j = 0; j < 4; j++)
                ldsm_x2(b[j], baseB + (uint32_t)(((nBase + j * 8 + lm8) * BSKC
                                                  + kks * 8 + lmb3 * 4) << 2));
#pragma unroll
            for (int i = 0; i < 4; i++)
#pragma unroll
                for (int j = 0; j < 4; j++)
                    mma_bf16(acc[i][j], a[i], b[j]);
        }
        __syncthreads();
        if (ik + 3 < nk) {
            ca_load(sbase + ((ik + 3) & 3) * CATILE,         Ag + (ik + 3) * 32, lda, tid);
            ca_load(sbase + ((ik + 3) & 3) * CATILE + 10240, Bg + (ik + 3) * 32, ldb, tid);
        }
        asm volatile("cp.async.commit_group;");
    }
}

// ===========================================================================
// cp.async 4-stage pipelined GEMM core, KT variant (k_scores)
// KT smem tile: 32 k-rows x 128 x-cols bf16, stride KTS=68 words (272 B).
// Per-stage: A 8704 B + B 8704 B = 17408 B; 4 stages = 69632 B.
// ===========================================================================
#define CAKT_TILE 17408
#define CAKT_SMEM (4 * CAKT_TILE)

__device__ __forceinline__ void ca_load_kt(uint32_t sdst, const __nv_bfloat16* g,
                                           int ld, int tid) {
    int row = tid >> 3;        // k-row 0..31
    int seg = tid & 7;         // 16B segment 0..7 (of 16)
    const char* gp = (const char*)g + (size_t)row * ld * 2;
    uint32_t sd = sdst + (uint32_t)row * (KTS * 4);
#pragma unroll
    for (int h = 0; h < 2; h++) {
        int sg = seg + h * 8;
        asm volatile("cp.async.cg.shared.global [%0], [%1], 16;"
                     :: "r"(sd + sg * 16), "l"(gp + sg * 16));
    }
}

__device__ __forceinline__ void gemm_ca_kt(const __nv_bfloat16* __restrict__ Ag,
                                           const __nv_bfloat16* __restrict__ Bg,
                                           int ld, int K, float acc[4][4][4],
                                           uint32_t sbase) {
    const int tid = threadIdx.x;
    const int warp = tid >> 5, lane = tid & 31;
    const int mBase = (warp >> 2) * 64;
    const int nBase = (warp & 3) * 32;
    const int l8 = lane & 7, lb3 = (lane >> 3) & 1, lb4 = (lane >> 4) & 1;
    const int lm = lane & 15, lm8 = lm & 7, lmb3 = (lm >> 3) & 1;

    const int nk = K >> 5;
#pragma unroll
    for (int s = 0; s < 3; s++) {
        if (s < nk) {
            ca_load_kt(sbase + s * CAKT_TILE,        Ag + (size_t)s * 32 * ld, ld, tid);
            ca_load_kt(sbase + s * CAKT_TILE + 8704, Bg + (size_t)s * 32 * ld, ld, tid);
        }
        asm volatile("cp.async.commit_group;");
    }
    for (int ik = 0; ik < nk; ik++) {
        asm volatile("cp.async.wait_group 2;");
        __syncthreads();
        const uint32_t baseA = sbase + (ik & 3) * CAKT_TILE;
        const uint32_t baseB = baseA + 8704;
#pragma unroll
        for (int kks = 0; kks < 2; kks++) {
            uint32_t a[4][4], b[4][2];
#pragma unroll
            for (int i = 0; i < 4; i++)
                ldsm_x4t(a[i], baseA + (uint32_t)(((kks * 16 + l8 + lb4 * 8) * KTS) << 2)
                               + (uint32_t)((mBase + i * 16 + lb3 * 8) << 1));
#pragma unroll
            for (int j = 0; j < 4; j++)
                ldsm_x2t(b[j], baseB + (uint32_t)(((kks * 16 + lm8 + lmb3 * 8) * KTS) << 2)
                               + (uint32_t)((nBase + j * 8) << 1));
#pragma unroll
            for (int i = 0; i < 4; i++)
#pragma unroll
                for (int j = 0; j < 4; j++)
                    mma_bf16(acc[i][j], a[i], b[j]);
        }
        __syncthreads();
        if (ik + 3 < nk) {
            ca_load_kt(sbase + ((ik + 3) & 3) * CAKT_TILE,
                       Ag + (size_t)(ik + 3) * 32 * ld, ld, tid);
            ca_load_kt(sbase + ((ik + 3) & 3) * CAKT_TILE + 8704,
                       Bg + (size_t)(ik + 3) * 32 * ld, ld, tid);
        }
        asm volatile("cp.async.commit_group;");
    }
}

// ---------------------------------------------------------------------------
// QKV: q,k,v written [C][T] channel-major
// ---------------------------------------------------------------------------
__global__ void __launch_bounds__(256, 2) k_qkv(const float* __restrict__ W,
                                                const float* __restrict__ bias,
                                                const float* __restrict__ x) {
    int n  = blockIdx.z;
    int m0 = blockIdx.y * 128;
    int t0 = blockIdx.x * 128;
    float acc[4][4][4] = {};
    gemm_bf<1, 3>(W + (size_t)m0 * C, C,
                  x + (size_t)n * C * T + t0, T, C, acc,
                  g_sc + n * C, g_sb + n * C);

    int which = m0 >> 9;
    __nv_bfloat16* dst =
        (which == 0 ? g_q : which == 1 ? g_k : g_v) + (size_t)n * C * T;
    int dbase = m0 & (C - 1);
    const int warp = threadIdx.x >> 5, lane = threadIdx.x & 31;
    const int g = lane >> 2, tg = lane & 3;
    const int mB = (warp >> 2) * 64, nB = (warp & 3) * 32;
#pragma unroll
    for (int i = 0; i < 4; i++) {
        int r = mB + i * 16 + g;
        float bv0 = bias[m0 + r];
        float bv1 = bias[m0 + r + 8];
#pragma unroll
        for (int j = 0; j < 4; j++) {
            int col = t0 + nB + j * 8 + tg * 2;
            uint32_t w0 = packbf(acc[i][j][0] + bv0, acc[i][j][1] + bv0);
            uint32_t w1 = packbf(acc[i][j][2] + bv1, acc[i][j][3] + bv1);
            *(uint32_t*)&dst[(size_t)(dbase + r) * T + col]     = w0;
            *(uint32_t*)&dst[(size_t)(dbase + r + 8) * T + col] = w1;
        }
    }
}

// ---------------------------------------------------------------------------
// scores: p[t][s] = exp(scale * q.k); per-(row, s-tile) sums -> g_lp
// (cp.async KT pipeline core)
// ---------------------------------------------------------------------------
__global__ void __launch_bounds__(256, 2) k_scores() {
    extern __shared__ char smraw[];
    uint32_t sbase = (uint32_t)__cvta_generic_to_shared(smraw);
    int n  = blockIdx.z;
    int t0 = blockIdx.y * 128;
    int s0 = blockIdx.x * 128;
    float acc[4][4][4] = {};
    gemm_ca_kt(g_q + (size_t)n * C * T + t0,
               g_k + (size_t)n * C * T + s0, T, C, acc, sbase);

    const float scale = 0.04419417382415922f;  // 512^-0.5
    __nv_bfloat16* dst = g_p + (size_t)n * T * T;
    __shared__ float sm_l[128][4];
    const int warp = threadIdx.x >> 5, lane = threadIdx.x & 31;
    const int g = lane >> 2, tg = lane & 3;
    const int mB = (warp >> 2) * 64, nB = (warp & 3) * 32;
#pragma unroll
    for (int i = 0; i < 4; i++) {
        int r = t0 + mB + i * 16 + g;
        float ps0 = 0.f, ps1 = 0.f;
#pragma unroll
        for (int j = 0; j < 4; j++) {
            int col = s0 + nB + j * 8 + tg * 2;
            float e0 = __expf(acc[i][j][0] * scale);
            float e1 = __expf(acc[i][j][1] * scale);
            float e2 = __expf(acc[i][j][2] * scale);
            float e3 = __expf(acc[i][j][3] * scale);
            ps0 += e0 + e1;
            ps1 += e2 + e3;
            *(uint32_t*)&dst[(size_t)r * T + col]       = packbf(e0, e1);
            *(uint32_t*)&dst[(size_t)(r + 8) * T + col] = packbf(e2, e3);
        }
        ps0 += __shfl_xor_sync(0xffffffffu, ps0, 1);
        ps0 += __shfl_xor_sync(0xffffffffu, ps0, 2);
        ps1 += __shfl_xor_sync(0xffffffffu, ps1, 1);
        ps1 += __shfl_xor_sync(0xffffffffu, ps1, 2);
        if (tg == 0) {
            sm_l[mB + i * 16 + g][warp & 3]     = ps0;
            sm_l[mB + i * 16 + g + 8][warp & 3] = ps1;
        }
    }
    __syncthreads();
    if (threadIdx.x < 128) {
        float l = sm_l[threadIdx.x][0] + sm_l[threadIdx.x][1]
                + sm_l[threadIdx.x][2] + sm_l[threadIdx.x][3];
        g_lp[((size_t)n * 32 + blockIdx.x) * T + t0 + threadIdx.x] = l;
    }
}

// ---------------------------------------------------------------------------
// inv row sum (fixed order, deterministic)
// ---------------------------------------------------------------------------
__global__ void __launch_bounds__(256) k_lsum() {
    int idx = blockIdx.x * 256 + threadIdx.x;
    int n = idx >> 12, t = idx & (T - 1);
    const float* lp = g_lp + (size_t)n * 32 * T + t;
    float l = 0.f;
#pragma unroll
    for (int i = 0; i < 32; i++) l += lp[(size_t)i * T];
    g_li[idx] = 1.f / l;
}

// ---------------------------------------------------------------------------
// AV: o[t][c] = inv_l[t] * sum_s p[t][s] * v[c][s]  (cp.async KC pipeline)
// ---------------------------------------------------------------------------
__global__ void __launch_bounds__(256, 2) k_av() {
    extern __shared__ char smraw[];
    uint32_t sbase = (uint32_t)__cvta_generic_to_shared(smraw);
    int n  = blockIdx.z;
    int t0 = blockIdx.y * 128;
    int c0 = blockIdx.x * 128;
    float acc[4][4][4] = {};
    gemm_ca(g_p + ((size_t)n * T + t0) * T, T,
            g_v + ((size_t)n * C + c0) * T, T, T, acc, sbase);

    __nv_bfloat16* dst = g_o + (size_t)n * T * C;
    const int warp = threadIdx.x >> 5, lane = threadIdx.x & 31;
    const int g = lane >> 2, tg = lane & 3;
    const int mB = (warp >> 2) * 64, nB = (warp & 3) * 32;
#pragma unroll
    for (int i = 0; i < 4; i++) {
        int r = t0 + mB + i * 16 + g;
        float inv0 = g_li[n * T + r];
        float inv1 = g_li[n * T + r + 8];
#pragma unroll
        for (int j = 0; j < 4; j++) {
            int col = c0 + nB + j * 8 + tg * 2;
            uint32_t w0 = packbf(acc[i][j][0] * inv0, acc[i][j][1] * inv0);
            uint32_t w1 = packbf(acc[i][j][2] * inv1, acc[i][j][3] * inv1);
            *(uint32_t*)&dst[(size_t)r * C + col]       = w0;
            *(uint32_t*)&dst[(size_t)(r + 8) * C + col] = w1;
        }
    }
}

// ---------------------------------------------------------------------------
// proj: out[n][d][t] = proj_w[d][:] . o[t][:] + proj_b[d] + x[n][d][t]
// ---------------------------------------------------------------------------
__global__ void __launch_bounds__(256, 2) k_proj(const float* __restrict__ W,
                                                 const float* __restrict__ bias,
                                                 const float* __restrict__ x,
                                                 float* __restrict__ out) {
    int n  = blockIdx.z;
    int d0 = blockIdx.y * 128;
    int t0 = blockIdx.x * 128;
    float acc[4][4][4] = {};
    gemm_bf<1, 0>(W + (size_t)d0 * C, C,
                  g_o + (size_t)n * T * C + (size_t)t0 * C, C, C, acc);

    const int warp = threadIdx.x >> 5, lane = threadIdx.x & 31;
    const int g = lane >> 2, tg = lane & 3;
    const int mB = (warp >> 2) * 64, nB = (warp & 3) * 32;
#pragma unroll
    for (int i = 0; i < 4; i++) {
        int d = d0 + mB + i * 16 + g;
        float bv0 = bias[d];
        float bv1 = bias[d + 8];
#pragma unroll
        for (int j = 0; j < 4; j++) {
            int col = t0 + nB + j * 8 + tg * 2;
            size_t base0 = ((size_t)n * C + d) * T + col;
            size_t base1 = ((size_t)n * C + d + 8) * T + col;
            float2 x0 = *(const float2*)&x[base0];
            float2 x1 = *(const float2*)&x[base1];
            float2 v0 = { acc[i][j][0] + bv0 + x0.x, acc[i][j][1] + bv0 + x0.y };
            float2 v1 = { acc[i][j][2] + bv1 + x1.x, acc[i][j][3] + bv1 + x1.y };
            *(float2*)&out[base0] = v0;
            *(float2*)&out[base1] = v1;
        }
    }
}

// ---------------------------------------------------------------------------
extern "C" void kernel_launch(void* const* d_in, const int* in_sizes, int n_in,
                              void* d_out, int out_size) {
    const float* x      = (const float*)d_in[0];
    const float* gn_w   = (const float*)d_in[1];
    const float* gn_b   = (const float*)d_in[2];
    const float* qkv_w  = (const float*)d_in[3];
    const float* qkv_b  = (const float*)d_in[4];
    const float* proj_w = (const float*)d_in[5];
    const float* proj_b = (const float*)d_in[6];
    float* out = (float*)d_out;

    cudaFuncSetAttribute(k_av,     cudaFuncAttributeMaxDynamicSharedMemorySize, CA_SMEM);
    cudaFuncSetAttribute(k_scores, cudaFuncAttributeMaxDynamicSharedMemorySize, CAKT_SMEM);

    gn_stats<<<NB * GROUPS, 256>>>(x, gn_w, gn_b);
    k_qkv   <<<dim3(T / 128, (3 * C) / 128, NB), 256>>>(qkv_w, qkv_b, x);
    k_scores<<<dim3(T / 128, T / 128, NB), 256, CAKT_SMEM>>>();
    k_lsum  <<<NB * T / 256, 256>>>();
    k_av    <<<dim3(C / 128, T / 128, NB), 256, CA_SMEM>>>();
    k_proj  <<<dim3(T / 128, C / 128, NB), 256>>>(proj_w, proj_b, x, out);
}